// round 1
// baseline (speedup 1.0000x reference)
#include <cuda_runtime.h>
#include <cuda_bf16.h>

// Problem constants
#define BATCH 16384
#define NN    1024          // feature dim
#define EE    8             // experts
#define RR    64            // rank
#define ER    512           // E*R combined
#define LL    3             // layers
#define TB    32            // batch rows per CTA
#define NTHR  256

// Pre-transposed weights (static device scratch — no runtime allocation)
__device__ float g_Vt[LL * NN * ER];     // [l][n][er]   6 MB
__device__ float g_Ug[LL * ER * NN];     // [l][er][n]   6 MB
__device__ float g_Ct[LL * EE * RR * RR];// [l][e][s][r] 0.4 MB

// ---------------- packed f32x2 helpers ----------------
__device__ __forceinline__ unsigned long long pk2(float lo, float hi) {
    unsigned long long r;
    asm("mov.b64 %0, {%1, %2};" : "=l"(r) : "f"(lo), "f"(hi));
    return r;
}
__device__ __forceinline__ void upk2(unsigned long long v, float& lo, float& hi) {
    asm("mov.b64 {%0, %1}, %2;" : "=f"(lo), "=f"(hi) : "l"(v));
}
__device__ __forceinline__ unsigned long long fma2(unsigned long long a,
                                                   unsigned long long b,
                                                   unsigned long long c) {
    unsigned long long d;
    asm("fma.rn.f32x2 %0, %1, %2, %3;" : "=l"(d) : "l"(a), "l"(b), "l"(c));
    return d;
}

// ---------------- batched 32x32 tiled transpose ----------------
// src: [rows][cols] -> dst: [cols][rows]; all dims multiples of 32.
__device__ __forceinline__ void ttile(const float* __restrict__ src,
                                      float* __restrict__ dst,
                                      int rows, int cols) {
    __shared__ float tile[32][33];
    const int c0 = blockIdx.x * 32, r0 = blockIdx.y * 32;
    const int tx = threadIdx.x, ty = threadIdx.y;
#pragma unroll
    for (int k = 0; k < 4; k++) {
        int r = r0 + ty + k * 8;
        tile[ty + k * 8][tx] = src[(size_t)r * cols + c0 + tx];
    }
    __syncthreads();
#pragma unroll
    for (int k = 0; k < 4; k++) {
        int c = c0 + ty + k * 8;
        dst[(size_t)c * rows + r0 + tx] = tile[tx][ty + k * 8];
    }
}

__global__ void prepV(const float* __restrict__ V) {
    int l = blockIdx.z;   // V[l] : [ER=512][NN=1024] -> g_Vt[l] : [NN][ER]
    ttile(V + (size_t)l * ER * NN, g_Vt + (size_t)l * NN * ER, ER, NN);
}
__global__ void prepU(const float* __restrict__ U) {
    int b = blockIdx.z;   // U[(l,e)] : [NN][RR] -> g_Ug[(l,e)] : [RR][NN]
    ttile(U + (size_t)b * NN * RR, g_Ug + (size_t)b * RR * NN, NN, RR);
}
__global__ void prepC(const float* __restrict__ C) {
    int b = blockIdx.z;   // C[(l,e)] : [RR][RR] -> g_Ct[(l,e)] : [s][r]
    ttile(C + (size_t)b * RR * RR, g_Ct + (size_t)b * RR * RR, RR, RR);
}

// ---------------- fused per-tile 3-layer kernel ----------------
// SMEM layout (floats):
//   xs     [TB][NN]   = 32768   residual / current x_l
//   vs     [TB][ER]   = 16384   v -> relu(v) -> c' (gated)
//   ws     [8192]               panel buffer (weights / gw / Ct staging)
//   gatesS [TB][EE]   = 256
// total 57600 floats = 230400 bytes
__global__ void __launch_bounds__(NTHR, 1)
fused_crossnet(const float* __restrict__ x0g,
               const float* __restrict__ biasg,
               const float* __restrict__ gwg,
               float* __restrict__ outg) {
    extern __shared__ float sm[];
    float* xs     = sm;                 // 32768
    float* vs     = xs + TB * NN;       // 16384
    float* ws     = vs + TB * ER;       // 8192
    float* gatesS = ws + 8192;          // 256

    const int t = threadIdx.x;
    const int ty = t >> 6;              // 0..3  (8 rows each)
    const int tx = t & 63;              // 0..63 (col pairs)
    const size_t brow0 = (size_t)blockIdx.x * TB;
    const float* x0t = x0g + brow0 * NN;

    // load x0 tile -> xs  (x_l starts as x0)
#pragma unroll
    for (int i = 0; i < TB * NN / 4 / NTHR; i++)
        reinterpret_cast<float4*>(xs)[t + NTHR * i] =
            reinterpret_cast<const float4*>(x0t)[t + NTHR * i];
    __syncthreads();

    for (int l = 0; l < LL; l++) {
        // ---- stage gate weights [8][1024] into ws ----
#pragma unroll
        for (int i = 0; i < EE * NN / 4 / NTHR; i++)
            reinterpret_cast<float4*>(ws)[t + NTHR * i] =
                reinterpret_cast<const float4*>(gwg)[t + NTHR * i];
        __syncthreads();

        // ---- gates: warp w handles rows b = w*4..w*4+3 ----
        {
            const int w = t >> 5, lane = t & 31;
#pragma unroll
            for (int ib = 0; ib < 4; ib++) {
                const int b = w * 4 + ib;
                float p[EE];
#pragma unroll
                for (int e = 0; e < EE; e++) p[e] = 0.f;
#pragma unroll
                for (int i = 0; i < 8; i++) {
                    const int n4 = lane + 32 * i;
                    float4 xv = reinterpret_cast<const float4*>(xs + b * NN)[n4];
#pragma unroll
                    for (int e = 0; e < EE; e++) {
                        float4 wv = reinterpret_cast<const float4*>(ws + e * NN)[n4];
                        p[e] += xv.x * wv.x + xv.y * wv.y + xv.z * wv.z + xv.w * wv.w;
                    }
                }
#pragma unroll
                for (int off = 16; off > 0; off >>= 1)
#pragma unroll
                    for (int e = 0; e < EE; e++)
                        p[e] += __shfl_xor_sync(0xffffffffu, p[e], off);
                // softmax (every lane redundantly; lane 0 writes)
                float m = p[0];
#pragma unroll
                for (int e = 1; e < EE; e++) m = fmaxf(m, p[e]);
                float s = 0.f;
                float pe[EE];
#pragma unroll
                for (int e = 0; e < EE; e++) { pe[e] = __expf(p[e] - m); s += pe[e]; }
                float inv = 1.0f / s;
                if (lane == 0) {
#pragma unroll
                    for (int e = 0; e < EE; e++) gatesS[b * EE + e] = pe[e] * inv;
                }
            }
        }

        // ---- GEMM1: vs = relu(xs @ Vt[l])   [32,1024]x[1024,512] ----
        {
            const float* Vt = g_Vt + (size_t)l * NN * ER;
            unsigned long long acc[8][4];
#pragma unroll
            for (int i = 0; i < 8; i++)
#pragma unroll
                for (int j = 0; j < 4; j++) acc[i][j] = 0ULL;

            for (int kt = 0; kt < NN / 16; kt++) {
                __syncthreads();
                {
                    const float4* s4 = reinterpret_cast<const float4*>(Vt + (size_t)kt * 16 * ER);
                    float4* d4 = reinterpret_cast<float4*>(ws);
#pragma unroll
                    for (int i = 0; i < 8; i++) d4[t + NTHR * i] = s4[t + NTHR * i];
                }
                __syncthreads();
#pragma unroll
                for (int ki = 0; ki < 16; ki++) {
                    unsigned long long a[8];
#pragma unroll
                    for (int i = 0; i < 8; i++) {
                        float av = xs[(ty * 8 + i) * NN + kt * 16 + ki];
                        a[i] = pk2(av, av);
                    }
#pragma unroll
                    for (int j = 0; j < 4; j++) {
                        unsigned long long wv = *reinterpret_cast<const unsigned long long*>(
                            ws + ki * ER + tx * 2 + 128 * j);
#pragma unroll
                        for (int i = 0; i < 8; i++) acc[i][j] = fma2(a[i], wv, acc[i][j]);
                    }
                }
            }
            __syncthreads();
#pragma unroll
            for (int i = 0; i < 8; i++)
#pragma unroll
                for (int j = 0; j < 4; j++) {
                    float lo, hi; upk2(acc[i][j], lo, hi);
                    const int b = ty * 8 + i, c = tx * 2 + 128 * j;
                    vs[b * ER + c]     = fmaxf(lo, 0.f);
                    vs[b * ER + c + 1] = fmaxf(hi, 0.f);
                }
        }

        // ---- small GEMMs per expert: c' = gate * relu(Ct[e]^T-form @ relu(v)) ----
        {
            const float* Ct = g_Ct + ((size_t)l * EE) * RR * RR;
            const int ty2 = t >> 5;       // 0..7 -> rows b = ty2*4+i
            const int tx2 = t & 31;       // r = tx2, tx2+32
            for (int e = 0; e < EE; e++) {
                __syncthreads();
                {
                    const float4* s4 = reinterpret_cast<const float4*>(Ct + (size_t)e * RR * RR);
                    float4* d4 = reinterpret_cast<float4*>(ws);
#pragma unroll
                    for (int i = 0; i < RR * RR / 4 / NTHR; i++)
                        d4[t + NTHR * i] = s4[t + NTHR * i];
                }
                __syncthreads();
                float acc2[4][2];
#pragma unroll
                for (int i = 0; i < 4; i++) { acc2[i][0] = 0.f; acc2[i][1] = 0.f; }
#pragma unroll 8
                for (int s = 0; s < RR; s++) {
                    float w0 = ws[s * RR + tx2];
                    float w1 = ws[s * RR + tx2 + 32];
#pragma unroll
                    for (int i = 0; i < 4; i++) {
                        float av = vs[(ty2 * 4 + i) * ER + e * RR + s];
                        acc2[i][0] = fmaf(av, w0, acc2[i][0]);
                        acc2[i][1] = fmaf(av, w1, acc2[i][1]);
                    }
                }
                __syncthreads();   // all reads of this expert's vs slice done
#pragma unroll
                for (int i = 0; i < 4; i++) {
                    const int b = ty2 * 4 + i;
                    const float g = gatesS[b * EE + e];
                    vs[b * ER + e * RR + tx2]      = g * fmaxf(acc2[i][0], 0.f);
                    vs[b * ER + e * RR + tx2 + 32] = g * fmaxf(acc2[i][1], 0.f);
                }
            }
        }
        __syncthreads();

        // ---- GEMM2 + epilogue: x_l = x0*(c' @ Ug[l] + bias) + x_l ----
        {
            const float* Ug = g_Ug + (size_t)l * ER * NN;
            unsigned long long acc3[8][8];
#pragma unroll
            for (int i = 0; i < 8; i++)
#pragma unroll
                for (int j = 0; j < 8; j++) acc3[i][j] = 0ULL;

            for (int kt = 0; kt < ER / 8; kt++) {
                __syncthreads();
                {
                    const float4* s4 = reinterpret_cast<const float4*>(Ug + (size_t)kt * 8 * NN);
                    float4* d4 = reinterpret_cast<float4*>(ws);
#pragma unroll
                    for (int i = 0; i < 8; i++) d4[t + NTHR * i] = s4[t + NTHR * i];
                }
                __syncthreads();
#pragma unroll
                for (int ki = 0; ki < 8; ki++) {
                    unsigned long long a[8];
#pragma unroll
                    for (int i = 0; i < 8; i++) {
                        float av = vs[(ty * 8 + i) * ER + kt * 8 + ki];
                        a[i] = pk2(av, av);
                    }
#pragma unroll
                    for (int j = 0; j < 8; j++) {
                        unsigned long long wv = *reinterpret_cast<const unsigned long long*>(
                            ws + ki * NN + tx * 2 + 128 * j);
#pragma unroll
                        for (int i = 0; i < 8; i++) acc3[i][j] = fma2(a[i], wv, acc3[i][j]);
                    }
                }
            }
            __syncthreads();
            // epilogue
#pragma unroll
            for (int i = 0; i < 8; i++) {
                const int b = ty * 8 + i;
#pragma unroll
                for (int j = 0; j < 8; j++) {
                    const int n = tx * 2 + 128 * j;
                    float lo, hi; upk2(acc3[i][j], lo, hi);
                    float2 bi  = *reinterpret_cast<const float2*>(biasg + l * NN + n);
                    float2 x0v = *reinterpret_cast<const float2*>(x0t + (size_t)b * NN + n);
                    float r0 = fmaf(x0v.x, lo + bi.x, xs[b * NN + n]);
                    float r1 = fmaf(x0v.y, hi + bi.y, xs[b * NN + n + 1]);
                    xs[b * NN + n]     = r0;
                    xs[b * NN + n + 1] = r1;
                    if (l == LL - 1) {
                        *reinterpret_cast<float2*>(outg + (brow0 + b) * NN + n) =
                            make_float2(r0, r1);
                    }
                }
            }
        }
        __syncthreads();   // ws/xs quiesce before next layer
    }
}

extern "C" void kernel_launch(void* const* d_in, const int* in_sizes, int n_in,
                              void* d_out, int out_size) {
    const float* x    = (const float*)d_in[0];
    const float* U    = (const float*)d_in[1];
    const float* V    = (const float*)d_in[2];
    const float* C    = (const float*)d_in[3];
    const float* bias = (const float*)d_in[4];
    const float* gw   = (const float*)d_in[5];
    float* out = (float*)d_out;

    // weight pre-transposes (deterministic, re-run each launch)
    dim3 tb(32, 8);
    prepV<<<dim3(NN / 32, ER / 32, LL), tb>>>(V);
    prepU<<<dim3(RR / 32, NN / 32, LL * EE), tb>>>(U);
    prepC<<<dim3(RR / 32, RR / 32, LL * EE), tb>>>(C);

    const int smem = (TB * NN + TB * ER + 8192 + TB * EE) * (int)sizeof(float); // 230400
    static_assert((TB * NN + TB * ER + 8192 + TB * EE) * 4 == 230400, "smem layout");
    cudaFuncSetAttribute(fused_crossnet,
                         cudaFuncAttributeMaxDynamicSharedMemorySize, smem);
    fused_crossnet<<<BATCH / TB, NTHR, smem>>>(x, bias, gw, out);
}

// round 2
// speedup vs baseline: 1.0005x; 1.0005x over previous
#include <cuda_runtime.h>
#include <cuda_bf16.h>

// Problem constants
#define BATCH 16384
#define NN    1024          // feature dim
#define EE    8             // experts
#define RR    64            // rank
#define ER    512           // E*R combined
#define LL    3             // layers
#define TB    32            // batch rows per CTA
#define NTHR  256

// Pre-transposed weights (static device scratch — no runtime allocation)
__device__ float g_Vt[LL * NN * ER];     // [l][n][er]   6 MB
__device__ float g_Ug[LL * ER * NN];     // [l][er][n]   6 MB
__device__ float g_Ct[LL * EE * RR * RR];// [l][e][s][r] 0.4 MB

// ---------------- packed f32x2 helpers ----------------
__device__ __forceinline__ unsigned long long pk2(float lo, float hi) {
    unsigned long long r;
    asm("mov.b64 %0, {%1, %2};" : "=l"(r) : "f"(lo), "f"(hi));
    return r;
}
__device__ __forceinline__ void upk2(unsigned long long v, float& lo, float& hi) {
    asm("mov.b64 {%0, %1}, %2;" : "=f"(lo), "=f"(hi) : "l"(v));
}
__device__ __forceinline__ unsigned long long fma2(unsigned long long a,
                                                   unsigned long long b,
                                                   unsigned long long c) {
    unsigned long long d;
    asm("fma.rn.f32x2 %0, %1, %2, %3;" : "=l"(d) : "l"(a), "l"(b), "l"(c));
    return d;
}

// ---------------- batched 32x32 tiled transpose ----------------
// src: [rows][cols] -> dst: [cols][rows]; all dims multiples of 32.
__device__ __forceinline__ void ttile(const float* __restrict__ src,
                                      float* __restrict__ dst,
                                      int rows, int cols) {
    __shared__ float tile[32][33];
    const int c0 = blockIdx.x * 32, r0 = blockIdx.y * 32;
    const int tx = threadIdx.x, ty = threadIdx.y;
#pragma unroll
    for (int k = 0; k < 4; k++) {
        int r = r0 + ty + k * 8;
        tile[ty + k * 8][tx] = src[(size_t)r * cols + c0 + tx];
    }
    __syncthreads();
#pragma unroll
    for (int k = 0; k < 4; k++) {
        int c = c0 + ty + k * 8;
        dst[(size_t)c * rows + r0 + tx] = tile[tx][ty + k * 8];
    }
}

__global__ void prepV(const float* __restrict__ V) {
    int l = blockIdx.z;   // V[l] : [ER=512][NN=1024] -> g_Vt[l] : [NN][ER]
    ttile(V + (size_t)l * ER * NN, g_Vt + (size_t)l * NN * ER, ER, NN);
}
__global__ void prepU(const float* __restrict__ U) {
    int b = blockIdx.z;   // U[(l,e)] : [NN][RR] -> g_Ug[(l,e)] : [RR][NN]
    ttile(U + (size_t)b * NN * RR, g_Ug + (size_t)b * RR * NN, NN, RR);
}
__global__ void prepC(const float* __restrict__ C) {
    int b = blockIdx.z;   // C[(l,e)] : [RR][RR] -> g_Ct[(l,e)] : [s][r]
    ttile(C + (size_t)b * RR * RR, g_Ct + (size_t)b * RR * RR, RR, RR);
}

// ---------------- fused per-tile 3-layer kernel ----------------
// SMEM layout (floats):
//   xs     [TB][NN]   = 32768   residual / current x_l
//   vs     [TB][ER]   = 16384   v -> relu(v) -> c' (gated)
//   ws     [8192]               panel buffer (weights / gw / Ct staging)
//   gatesS [TB][EE]   = 256
// total 57600 floats = 230400 bytes
__global__ void __launch_bounds__(NTHR, 1)
fused_crossnet(const float* __restrict__ x0g,
               const float* __restrict__ biasg,
               const float* __restrict__ gwg,
               float* __restrict__ outg) {
    extern __shared__ float sm[];
    float* xs     = sm;                 // 32768
    float* vs     = xs + TB * NN;       // 16384
    float* ws     = vs + TB * ER;       // 8192
    float* gatesS = ws + 8192;          // 256

    const int t = threadIdx.x;
    const int ty = t >> 6;              // 0..3  (8 rows each)
    const int tx = t & 63;              // 0..63 (col pairs)
    const size_t brow0 = (size_t)blockIdx.x * TB;
    const float* x0t = x0g + brow0 * NN;

    // load x0 tile -> xs  (x_l starts as x0)
#pragma unroll
    for (int i = 0; i < TB * NN / 4 / NTHR; i++)
        reinterpret_cast<float4*>(xs)[t + NTHR * i] =
            reinterpret_cast<const float4*>(x0t)[t + NTHR * i];
    __syncthreads();

    for (int l = 0; l < LL; l++) {
        // ---- stage gate weights [8][1024] into ws ----
#pragma unroll
        for (int i = 0; i < EE * NN / 4 / NTHR; i++)
            reinterpret_cast<float4*>(ws)[t + NTHR * i] =
                reinterpret_cast<const float4*>(gwg)[t + NTHR * i];
        __syncthreads();

        // ---- gates: warp w handles rows b = w*4..w*4+3 ----
        {
            const int w = t >> 5, lane = t & 31;
#pragma unroll
            for (int ib = 0; ib < 4; ib++) {
                const int b = w * 4 + ib;
                float p[EE];
#pragma unroll
                for (int e = 0; e < EE; e++) p[e] = 0.f;
#pragma unroll
                for (int i = 0; i < 8; i++) {
                    const int n4 = lane + 32 * i;
                    float4 xv = reinterpret_cast<const float4*>(xs + b * NN)[n4];
#pragma unroll
                    for (int e = 0; e < EE; e++) {
                        float4 wv = reinterpret_cast<const float4*>(ws + e * NN)[n4];
                        p[e] += xv.x * wv.x + xv.y * wv.y + xv.z * wv.z + xv.w * wv.w;
                    }
                }
#pragma unroll
                for (int off = 16; off > 0; off >>= 1)
#pragma unroll
                    for (int e = 0; e < EE; e++)
                        p[e] += __shfl_xor_sync(0xffffffffu, p[e], off);
                // softmax (every lane redundantly; lane 0 writes)
                float m = p[0];
#pragma unroll
                for (int e = 1; e < EE; e++) m = fmaxf(m, p[e]);
                float s = 0.f;
                float pe[EE];
#pragma unroll
                for (int e = 0; e < EE; e++) { pe[e] = __expf(p[e] - m); s += pe[e]; }
                float inv = 1.0f / s;
                if (lane == 0) {
#pragma unroll
                    for (int e = 0; e < EE; e++) gatesS[b * EE + e] = pe[e] * inv;
                }
            }
        }

        // ---- GEMM1: vs = relu(xs @ Vt[l])   [32,1024]x[1024,512] ----
        {
            const float* Vt = g_Vt + (size_t)l * NN * ER;
            unsigned long long acc[8][4];
#pragma unroll
            for (int i = 0; i < 8; i++)
#pragma unroll
                for (int j = 0; j < 4; j++) acc[i][j] = 0ULL;

            for (int kt = 0; kt < NN / 16; kt++) {
                __syncthreads();
                {
                    const float4* s4 = reinterpret_cast<const float4*>(Vt + (size_t)kt * 16 * ER);
                    float4* d4 = reinterpret_cast<float4*>(ws);
#pragma unroll
                    for (int i = 0; i < 8; i++) d4[t + NTHR * i] = s4[t + NTHR * i];
                }
                __syncthreads();
#pragma unroll
                for (int ki = 0; ki < 16; ki++) {
                    unsigned long long a[8];
#pragma unroll
                    for (int i = 0; i < 8; i++) {
                        float av = xs[(ty * 8 + i) * NN + kt * 16 + ki];
                        a[i] = pk2(av, av);
                    }
#pragma unroll
                    for (int j = 0; j < 4; j++) {
                        unsigned long long wv = *reinterpret_cast<const unsigned long long*>(
                            ws + ki * ER + tx * 2 + 128 * j);
#pragma unroll
                        for (int i = 0; i < 8; i++) acc[i][j] = fma2(a[i], wv, acc[i][j]);
                    }
                }
            }
            __syncthreads();
#pragma unroll
            for (int i = 0; i < 8; i++)
#pragma unroll
                for (int j = 0; j < 4; j++) {
                    float lo, hi; upk2(acc[i][j], lo, hi);
                    const int b = ty * 8 + i, c = tx * 2 + 128 * j;
                    vs[b * ER + c]     = fmaxf(lo, 0.f);
                    vs[b * ER + c + 1] = fmaxf(hi, 0.f);
                }
        }

        // ---- small GEMMs per expert: c' = gate * relu(Ct[e]^T-form @ relu(v)) ----
        {
            const float* Ct = g_Ct + ((size_t)l * EE) * RR * RR;
            const int ty2 = t >> 5;       // 0..7 -> rows b = ty2*4+i
            const int tx2 = t & 31;       // r = tx2, tx2+32
            for (int e = 0; e < EE; e++) {
                __syncthreads();
                {
                    const float4* s4 = reinterpret_cast<const float4*>(Ct + (size_t)e * RR * RR);
                    float4* d4 = reinterpret_cast<float4*>(ws);
#pragma unroll
                    for (int i = 0; i < RR * RR / 4 / NTHR; i++)
                        d4[t + NTHR * i] = s4[t + NTHR * i];
                }
                __syncthreads();
                float acc2[4][2];
#pragma unroll
                for (int i = 0; i < 4; i++) { acc2[i][0] = 0.f; acc2[i][1] = 0.f; }
#pragma unroll 8
                for (int s = 0; s < RR; s++) {
                    float w0 = ws[s * RR + tx2];
                    float w1 = ws[s * RR + tx2 + 32];
#pragma unroll
                    for (int i = 0; i < 4; i++) {
                        float av = vs[(ty2 * 4 + i) * ER + e * RR + s];
                        acc2[i][0] = fmaf(av, w0, acc2[i][0]);
                        acc2[i][1] = fmaf(av, w1, acc2[i][1]);
                    }
                }
                __syncthreads();   // all reads of this expert's vs slice done
#pragma unroll
                for (int i = 0; i < 4; i++) {
                    const int b = ty2 * 4 + i;
                    const float g = gatesS[b * EE + e];
                    vs[b * ER + e * RR + tx2]      = g * fmaxf(acc2[i][0], 0.f);
                    vs[b * ER + e * RR + tx2 + 32] = g * fmaxf(acc2[i][1], 0.f);
                }
            }
        }
        __syncthreads();

        // ---- GEMM2 + epilogue: x_l = x0*(c' @ Ug[l] + bias) + x_l ----
        {
            const float* Ug = g_Ug + (size_t)l * ER * NN;
            unsigned long long acc3[8][8];
#pragma unroll
            for (int i = 0; i < 8; i++)
#pragma unroll
                for (int j = 0; j < 8; j++) acc3[i][j] = 0ULL;

            for (int kt = 0; kt < ER / 8; kt++) {
                __syncthreads();
                {
                    const float4* s4 = reinterpret_cast<const float4*>(Ug + (size_t)kt * 8 * NN);
                    float4* d4 = reinterpret_cast<float4*>(ws);
#pragma unroll
                    for (int i = 0; i < 8; i++) d4[t + NTHR * i] = s4[t + NTHR * i];
                }
                __syncthreads();
#pragma unroll
                for (int ki = 0; ki < 8; ki++) {
                    unsigned long long a[8];
#pragma unroll
                    for (int i = 0; i < 8; i++) {
                        float av = vs[(ty * 8 + i) * ER + kt * 8 + ki];
                        a[i] = pk2(av, av);
                    }
#pragma unroll
                    for (int j = 0; j < 8; j++) {
                        unsigned long long wv = *reinterpret_cast<const unsigned long long*>(
                            ws + ki * NN + tx * 2 + 128 * j);
#pragma unroll
                        for (int i = 0; i < 8; i++) acc3[i][j] = fma2(a[i], wv, acc3[i][j]);
                    }
                }
            }
            __syncthreads();
            // epilogue
#pragma unroll
            for (int i = 0; i < 8; i++) {
                const int b = ty * 8 + i;
#pragma unroll
                for (int j = 0; j < 8; j++) {
                    const int n = tx * 2 + 128 * j;
                    float lo, hi; upk2(acc3[i][j], lo, hi);
                    float2 bi  = *reinterpret_cast<const float2*>(biasg + l * NN + n);
                    float2 x0v = *reinterpret_cast<const float2*>(x0t + (size_t)b * NN + n);
                    float r0 = fmaf(x0v.x, lo + bi.x, xs[b * NN + n]);
                    float r1 = fmaf(x0v.y, hi + bi.y, xs[b * NN + n + 1]);
                    xs[b * NN + n]     = r0;
                    xs[b * NN + n + 1] = r1;
                    if (l == LL - 1) {
                        *reinterpret_cast<float2*>(outg + (brow0 + b) * NN + n) =
                            make_float2(r0, r1);
                    }
                }
            }
        }
        __syncthreads();   // ws/xs quiesce before next layer
    }
}

extern "C" void kernel_launch(void* const* d_in, const int* in_sizes, int n_in,
                              void* d_out, int out_size) {
    const float* x    = (const float*)d_in[0];
    const float* U    = (const float*)d_in[1];
    const float* V    = (const float*)d_in[2];
    const float* C    = (const float*)d_in[3];
    const float* bias = (const float*)d_in[4];
    const float* gw   = (const float*)d_in[5];
    float* out = (float*)d_out;

    // weight pre-transposes (deterministic, re-run each launch)
    dim3 tb(32, 8);
    prepV<<<dim3(NN / 32, ER / 32, LL), tb>>>(V);
    prepU<<<dim3(RR / 32, NN / 32, LL * EE), tb>>>(U);
    prepC<<<dim3(RR / 32, RR / 32, LL * EE), tb>>>(C);

    const int smem = (TB * NN + TB * ER + 8192 + TB * EE) * (int)sizeof(float); // 230400
    static_assert((TB * NN + TB * ER + 8192 + TB * EE) * 4 == 230400, "smem layout");
    cudaFuncSetAttribute(fused_crossnet,
                         cudaFuncAttributeMaxDynamicSharedMemorySize, smem);
    fused_crossnet<<<BATCH / TB, NTHR, smem>>>(x, bias, gw, out);
}

// round 4
// speedup vs baseline: 2.0737x; 2.0728x over previous
#include <cuda_runtime.h>
#include <cuda_bf16.h>
#include <cstdint>

#define BATCH 16384
#define NN    1024
#define EE    8
#define RR    64
#define ER    512
#define LL    3

// ---------------- static device scratch ----------------
__device__ float          g_xcur[BATCH * NN];
__device__ float          g_gates[BATCH * EE];
__device__ __nv_bfloat16  g_xh[BATCH * NN],  g_xl[BATCH * NN];
__device__ __nv_bfloat16  g_cph[BATCH * ER], g_cpl[BATCH * ER];
__device__ __nv_bfloat16  g_Vh[LL * ER * NN], g_Vl[LL * ER * NN];
__device__ __nv_bfloat16  g_Uh[LL * NN * ER], g_Ul[LL * NN * ER];
__device__ __nv_bfloat16  g_Ch[LL * EE * RR * RR], g_Cl[LL * EE * RR * RR];

// ---------------- helpers ----------------
__device__ __forceinline__ uint32_t smem_u32(const void* p) {
    uint32_t a;
    asm("{ .reg .u64 t; cvta.to.shared.u64 t, %1; cvt.u32.u64 %0, t; }" : "=r"(a) : "l"(p));
    return a;
}
__device__ __forceinline__ void ldsm4(uint32_t* r, uint32_t addr) {
    asm volatile("ldmatrix.sync.aligned.m8n8.x4.shared.b16 {%0,%1,%2,%3}, [%4];"
                 : "=r"(r[0]), "=r"(r[1]), "=r"(r[2]), "=r"(r[3]) : "r"(addr));
}
__device__ __forceinline__ void mma_bf16(float* d, const uint32_t* a, const uint32_t* b) {
    asm volatile(
        "mma.sync.aligned.m16n8k16.row.col.f32.bf16.bf16.f32 "
        "{%0,%1,%2,%3}, {%4,%5,%6,%7}, {%8,%9}, {%0,%1,%2,%3};"
        : "+f"(d[0]), "+f"(d[1]), "+f"(d[2]), "+f"(d[3])
        : "r"(a[0]), "r"(a[1]), "r"(a[2]), "r"(a[3]), "r"(b[0]), "r"(b[1]));
}
// split a,b into packed bf16x2 hi and lo
__device__ __forceinline__ void bsplit2(float a, float b, uint32_t& hi, uint32_t& lo) {
    __nv_bfloat16 ha = __float2bfloat16(a), hb = __float2bfloat16(b);
    __nv_bfloat16 la = __float2bfloat16(a - __bfloat162float(ha));
    __nv_bfloat16 lb = __float2bfloat16(b - __bfloat162float(hb));
    hi = (uint32_t)__bfloat16_as_ushort(ha) | ((uint32_t)__bfloat16_as_ushort(hb) << 16);
    lo = (uint32_t)__bfloat16_as_ushort(la) | ((uint32_t)__bfloat16_as_ushort(lb) << 16);
}

// ---------------- prep kernels ----------------
__global__ void prep_x(const float* __restrict__ x) {
    int i = blockIdx.x * 256 + threadIdx.x;
    uint32_t h, l;
    bsplit2(x[i], 0.f, h, l);
    g_xh[i] = __ushort_as_bfloat16((unsigned short)(h & 0xffff));
    g_xl[i] = __ushort_as_bfloat16((unsigned short)(l & 0xffff));
}
__global__ void prepV_k(const float* __restrict__ V) {
    int i = blockIdx.x * 256 + threadIdx.x;
    uint32_t h, l;
    bsplit2(V[i], 0.f, h, l);
    g_Vh[i] = __ushort_as_bfloat16((unsigned short)(h & 0xffff));
    g_Vl[i] = __ushort_as_bfloat16((unsigned short)(l & 0xffff));
}
__global__ void prepC_k(const float* __restrict__ C) {
    int i = blockIdx.x * 256 + threadIdx.x;
    uint32_t h, l;
    bsplit2(C[i], 0.f, h, l);
    g_Ch[i] = __ushort_as_bfloat16((unsigned short)(h & 0xffff));
    g_Cl[i] = __ushort_as_bfloat16((unsigned short)(l & 0xffff));
}
__global__ void prepU_k(const float* __restrict__ U) {
    int o = blockIdx.x * 256 + threadIdx.x;     // o = (l*NN + n)*ER + er
    int er = o & 511, n = (o >> 9) & 1023, l = o >> 19;
    float f = U[(((size_t)(l * EE + (er >> 6))) * NN + n) * RR + (er & 63)];
    uint32_t h, lo;
    bsplit2(f, 0.f, h, lo);
    g_Uh[o] = __ushort_as_bfloat16((unsigned short)(h & 0xffff));
    g_Ul[o] = __ushort_as_bfloat16((unsigned short)(lo & 0xffff));
}

// ---------------- gates (exact fp32) ----------------
__global__ void gates_k(const float* __restrict__ x_in, const float* __restrict__ gw, int l) {
    const float* xl = l ? g_xcur : x_in;
    int w = threadIdx.x >> 5, lane = threadIdx.x & 31;
    size_t row = (size_t)blockIdx.x * 8 + w;
    const float4* xr = (const float4*)(xl + row * NN);
    float acc[EE];
#pragma unroll
    for (int e = 0; e < EE; e++) acc[e] = 0.f;
#pragma unroll
    for (int i = 0; i < 8; i++) {
        float4 xv = xr[i * 32 + lane];
#pragma unroll
        for (int e = 0; e < EE; e++) {
            float4 wv = ((const float4*)(gw + e * NN))[i * 32 + lane];
            acc[e] += xv.x * wv.x + xv.y * wv.y + xv.z * wv.z + xv.w * wv.w;
        }
    }
#pragma unroll
    for (int off = 16; off > 0; off >>= 1)
#pragma unroll
        for (int e = 0; e < EE; e++) acc[e] += __shfl_xor_sync(0xffffffffu, acc[e], off);
    if (lane == 0) {
        float m = acc[0];
#pragma unroll
        for (int e = 1; e < EE; e++) m = fmaxf(m, acc[e]);
        float s = 0.f, pe[EE];
#pragma unroll
        for (int e = 0; e < EE; e++) { pe[e] = __expf(acc[e] - m); s += pe[e]; }
        float inv = 1.0f / s;
#pragma unroll
        for (int e = 0; e < EE; e++) g_gates[row * EE + e] = pe[e] * inv;
    }
}

// ---------------- shared MMA block: 128x128 tile, one k32 chunk ----------------
// SMEM chunk layout (per buffer): Ah[128][32] pitch 80B, Al +10240, Bh +20480, Bl +30720
__device__ __forceinline__ void mma_block(uint32_t base, int wm, int wn, int lr, int kc,
                                          float d[2][8][4]) {
    const uint32_t Ah = base, Al = base + 10240, Bh = base + 20480, Bl = base + 30720;
#pragma unroll
    for (int q = 0; q < 2; q++) {
        uint32_t ah[2][4], al[2][4];
#pragma unroll
        for (int i = 0; i < 2; i++) {
            uint32_t ra = (uint32_t)((wm + i * 16 + lr) * 80 + (q * 16 + kc) * 2);
            ldsm4(ah[i], Ah + ra);
            ldsm4(al[i], Al + ra);
        }
        uint32_t bh[8][2], bl[8][2];
#pragma unroll
        for (int jj = 0; jj < 4; jj++) {
            uint32_t rb = (uint32_t)((wn + jj * 16 + lr) * 80 + (q * 16 + kc) * 2);
            uint32_t tp[4];
            ldsm4(tp, Bh + rb);
            bh[2 * jj][0] = tp[0]; bh[2 * jj + 1][0] = tp[1];
            bh[2 * jj][1] = tp[2]; bh[2 * jj + 1][1] = tp[3];
            ldsm4(tp, Bl + rb);
            bl[2 * jj][0] = tp[0]; bl[2 * jj + 1][0] = tp[1];
            bl[2 * jj][1] = tp[2]; bl[2 * jj + 1][1] = tp[3];
        }
#pragma unroll
        for (int i = 0; i < 2; i++)
#pragma unroll
            for (int j = 0; j < 8; j++) {
                mma_bf16(d[i][j], ah[i], bh[j]);
                mma_bf16(d[i][j], ah[i], bl[j]);
                mma_bf16(d[i][j], al[i], bh[j]);
            }
    }
}

// expert block: A = rv tiles (pitch 144B, 64 k), B = C tiles (pitch 144B)
#define RV_OFF(el)  ((el) * 36864)
#define CT_OFF(el)  (73728 + (el) * 18432)
__device__ __forceinline__ void mma_expert(uint32_t sb, int el, int mb, int lr, int kc,
                                           float d[2][8][4]) {
    const uint32_t Ah = sb + RV_OFF(el), Al = Ah + 18432;
    const uint32_t Bh = sb + CT_OFF(el), Bl = Bh + 9216;
#pragma unroll
    for (int q = 0; q < 4; q++) {
        uint32_t ah[2][4], al[2][4];
#pragma unroll
        for (int i = 0; i < 2; i++) {
            uint32_t ra = (uint32_t)((mb + i * 16 + lr) * 144 + (q * 16 + kc) * 2);
            ldsm4(ah[i], Ah + ra);
            ldsm4(al[i], Al + ra);
        }
        uint32_t bh[8][2], bl[8][2];
#pragma unroll
        for (int jj = 0; jj < 4; jj++) {
            uint32_t rb = (uint32_t)((jj * 16 + lr) * 144 + (q * 16 + kc) * 2);
            uint32_t tp[4];
            ldsm4(tp, Bh + rb);
            bh[2 * jj][0] = tp[0]; bh[2 * jj + 1][0] = tp[1];
            bh[2 * jj][1] = tp[2]; bh[2 * jj + 1][1] = tp[3];
            ldsm4(tp, Bl + rb);
            bl[2 * jj][0] = tp[0]; bl[2 * jj + 1][0] = tp[1];
            bl[2 * jj][1] = tp[2]; bl[2 * jj + 1][1] = tp[3];
        }
#pragma unroll
        for (int i = 0; i < 2; i++)
#pragma unroll
            for (int j = 0; j < 8; j++) {
                mma_bf16(d[i][j], ah[i], bh[j]);
                mma_bf16(d[i][j], ah[i], bl[j]);
                mma_bf16(d[i][j], al[i], bh[j]);
            }
    }
}

// =====================================================================
// GEMM1 (v = x @ V^T) fused with expert chain -> c' hi/lo
// grid (BATCH/128, 4), 256 threads
// =====================================================================
__global__ void __launch_bounds__(256) gemm1_k(int l) {
    extern __shared__ char smc[];
    const uint32_t sb = smem_u32(smc);
    const int t = threadIdx.x, w = t >> 5, lane = t & 31;
    const int lr = lane & 15, kc = (lane >> 4) * 8, g = lane >> 2, tig = lane & 3;
    const int wm = (w & 3) * 32, wn = (w >> 2) * 64;
    const size_t brow0 = (size_t)blockIdx.x * 128;
    const int no = blockIdx.y * 128;
    const int sr = t >> 1;
    const uint32_t so = (uint32_t)(sr * 80 + (t & 1) * 32);

    const __nv_bfloat16* pAh = g_xh + (brow0 + sr) * NN + (t & 1) * 16;
    const __nv_bfloat16* pAl = g_xl + (brow0 + sr) * NN + (t & 1) * 16;
    const __nv_bfloat16* pBh = g_Vh + (size_t)l * ER * NN + (size_t)(no + sr) * NN + (t & 1) * 16;
    const __nv_bfloat16* pBl = g_Vl + (size_t)l * ER * NN + (size_t)(no + sr) * NN + (t & 1) * 16;

    float d[2][8][4];
#pragma unroll
    for (int i = 0; i < 2; i++)
#pragma unroll
        for (int j = 0; j < 8; j++)
#pragma unroll
            for (int k = 0; k < 4; k++) d[i][j][k] = 0.f;

    uint4 a0, a1, a2, a3, b0, b1, b2, b3;
    a0 = *(const uint4*)(pAh); a1 = *(const uint4*)(pAh + 8);
    a2 = *(const uint4*)(pAl); a3 = *(const uint4*)(pAl + 8);
    b0 = *(const uint4*)(pBh); b1 = *(const uint4*)(pBh + 8);
    b2 = *(const uint4*)(pBl); b3 = *(const uint4*)(pBl + 8);
    *(uint4*)(smc + so) = a0;          *(uint4*)(smc + so + 16) = a1;
    *(uint4*)(smc + 10240 + so) = a2;  *(uint4*)(smc + 10240 + so + 16) = a3;
    *(uint4*)(smc + 20480 + so) = b0;  *(uint4*)(smc + 20480 + so + 16) = b1;
    *(uint4*)(smc + 30720 + so) = b2;  *(uint4*)(smc + 30720 + so + 16) = b3;
    __syncthreads();

    for (int kt = 0; kt < 32; kt++) {
        const uint32_t cur = (uint32_t)(kt & 1) * 40960u;
        const uint32_t nxt = cur ^ 40960u;
        if (kt < 31) {
            int o = (kt + 1) * 32;
            a0 = *(const uint4*)(pAh + o); a1 = *(const uint4*)(pAh + o + 8);
            a2 = *(const uint4*)(pAl + o); a3 = *(const uint4*)(pAl + o + 8);
            b0 = *(const uint4*)(pBh + o); b1 = *(const uint4*)(pBh + o + 8);
            b2 = *(const uint4*)(pBl + o); b3 = *(const uint4*)(pBl + o + 8);
        }
        mma_block(sb + cur, wm, wn, lr, kc, d);
        if (kt < 31) {
            *(uint4*)(smc + nxt + so) = a0;          *(uint4*)(smc + nxt + so + 16) = a1;
            *(uint4*)(smc + nxt + 10240 + so) = a2;  *(uint4*)(smc + nxt + 10240 + so + 16) = a3;
            *(uint4*)(smc + nxt + 20480 + so) = b0;  *(uint4*)(smc + nxt + 20480 + so + 16) = b1;
            *(uint4*)(smc + nxt + 30720 + so) = b2;  *(uint4*)(smc + nxt + 30720 + so + 16) = b3;
        }
        __syncthreads();
    }

    // ---- write relu(v) split into rv tiles (pitch 144) ----
    {
        const int el = w >> 2;
        const uint32_t rvh = RV_OFF(el), rvl = rvh + 18432;
#pragma unroll
        for (int i = 0; i < 2; i++) {
            int r0 = wm + i * 16 + g;
#pragma unroll
            for (int j = 0; j < 8; j++) {
                int sc = j * 8 + 2 * tig;
                uint32_t h0, l0, h1, l1;
                bsplit2(fmaxf(d[i][j][0], 0.f), fmaxf(d[i][j][1], 0.f), h0, l0);
                bsplit2(fmaxf(d[i][j][2], 0.f), fmaxf(d[i][j][3], 0.f), h1, l1);
                uint32_t o0 = (uint32_t)(r0 * 144 + sc * 2);
                uint32_t o1 = o0 + 8 * 144;
                *(uint32_t*)(smc + rvh + o0) = h0;
                *(uint32_t*)(smc + rvh + o1) = h1;
                *(uint32_t*)(smc + rvl + o0) = l0;
                *(uint32_t*)(smc + rvl + o1) = l1;
            }
        }
    }
    // ---- load C tiles (2 experts) ----
    {
        int el = t >> 7, h = (t >> 6) & 1, r = t & 63;
        const __nv_bfloat16* src = (h ? g_Cl : g_Ch) +
            ((size_t)(l * EE + blockIdx.y * 2 + el) * RR + r) * RR;
        uint32_t doff = (uint32_t)(CT_OFF(el) + h * 9216 + r * 144);
#pragma unroll
        for (int s4 = 0; s4 < 8; s4++)
            *(uint4*)(smc + doff + s4 * 16) = *(const uint4*)(src + s4 * 8);
    }
    __syncthreads();

    // ---- expert mma: c = rv @ C^T ----
#pragma unroll
    for (int i = 0; i < 2; i++)
#pragma unroll
        for (int j = 0; j < 8; j++)
#pragma unroll
            for (int k = 0; k < 4; k++) d[i][j][k] = 0.f;
    mma_expert(sb, w >> 2, wm, lr, kc, d);

    // ---- epilogue: c' = gate*relu(c) split -> global ----
    {
        const int el = w >> 2, e = blockIdx.y * 2 + el;
#pragma unroll
        for (int i = 0; i < 2; i++) {
            size_t r0 = brow0 + wm + i * 16 + g, r1 = r0 + 8;
            float g0 = g_gates[r0 * EE + e], g1 = g_gates[r1 * EE + e];
#pragma unroll
            for (int j = 0; j < 8; j++) {
                int cc = e * 64 + j * 8 + 2 * tig;
                uint32_t h0, l0, h1, l1;
                bsplit2(g0 * fmaxf(d[i][j][0], 0.f), g0 * fmaxf(d[i][j][1], 0.f), h0, l0);
                bsplit2(g1 * fmaxf(d[i][j][2], 0.f), g1 * fmaxf(d[i][j][3], 0.f), h1, l1);
                *(uint32_t*)(g_cph + r0 * ER + cc) = h0;
                *(uint32_t*)(g_cpl + r0 * ER + cc) = l0;
                *(uint32_t*)(g_cph + r1 * ER + cc) = h1;
                *(uint32_t*)(g_cpl + r1 * ER + cc) = l1;
            }
        }
    }
}

// =====================================================================
// GEMM2: x_next = x0 * (c' @ U^T + bias) + x_l ; also emits split x_next
// grid (BATCH/128, 8), 256 threads
// =====================================================================
__global__ void __launch_bounds__(256) gemm2_k(const float* __restrict__ x_in,
                                               const float* __restrict__ biasg,
                                               float* __restrict__ outg, int l) {
    extern __shared__ char smc[];
    const uint32_t sb = smem_u32(smc);
    const int t = threadIdx.x, w = t >> 5, lane = t & 31;
    const int lr = lane & 15, kc = (lane >> 4) * 8, g = lane >> 2, tig = lane & 3;
    const int wm = (w & 3) * 32, wn = (w >> 2) * 64;
    const size_t brow0 = (size_t)blockIdx.x * 128;
    const int no = blockIdx.y * 128;
    const int sr = t >> 1;
    const uint32_t so = (uint32_t)(sr * 80 + (t & 1) * 32);

    const __nv_bfloat16* pAh = g_cph + (brow0 + sr) * ER + (t & 1) * 16;
    const __nv_bfloat16* pAl = g_cpl + (brow0 + sr) * ER + (t & 1) * 16;
    const __nv_bfloat16* pBh = g_Uh + (size_t)l * NN * ER + (size_t)(no + sr) * ER + (t & 1) * 16;
    const __nv_bfloat16* pBl = g_Ul + (size_t)l * NN * ER + (size_t)(no + sr) * ER + (t & 1) * 16;

    float d[2][8][4];
#pragma unroll
    for (int i = 0; i < 2; i++)
#pragma unroll
        for (int j = 0; j < 8; j++)
#pragma unroll
            for (int k = 0; k < 4; k++) d[i][j][k] = 0.f;

    uint4 a0, a1, a2, a3, b0, b1, b2, b3;
    a0 = *(const uint4*)(pAh); a1 = *(const uint4*)(pAh + 8);
    a2 = *(const uint4*)(pAl); a3 = *(const uint4*)(pAl + 8);
    b0 = *(const uint4*)(pBh); b1 = *(const uint4*)(pBh + 8);
    b2 = *(const uint4*)(pBl); b3 = *(const uint4*)(pBl + 8);
    *(uint4*)(smc + so) = a0;          *(uint4*)(smc + so + 16) = a1;
    *(uint4*)(smc + 10240 + so) = a2;  *(uint4*)(smc + 10240 + so + 16) = a3;
    *(uint4*)(smc + 20480 + so) = b0;  *(uint4*)(smc + 20480 + so + 16) = b1;
    *(uint4*)(smc + 30720 + so) = b2;  *(uint4*)(smc + 30720 + so + 16) = b3;
    __syncthreads();

    for (int kt = 0; kt < 16; kt++) {
        const uint32_t cur = (uint32_t)(kt & 1) * 40960u;
        const uint32_t nxt = cur ^ 40960u;
        if (kt < 15) {
            int o = (kt + 1) * 32;
            a0 = *(const uint4*)(pAh + o); a1 = *(const uint4*)(pAh + o + 8);
            a2 = *(const uint4*)(pAl + o); a3 = *(const uint4*)(pAl + o + 8);
            b0 = *(const uint4*)(pBh + o); b1 = *(const uint4*)(pBh + o + 8);
            b2 = *(const uint4*)(pBl + o); b3 = *(const uint4*)(pBl + o + 8);
        }
        mma_block(sb + cur, wm, wn, lr, kc, d);
        if (kt < 15) {
            *(uint4*)(smc + nxt + so) = a0;          *(uint4*)(smc + nxt + so + 16) = a1;
            *(uint4*)(smc + nxt + 10240 + so) = a2;  *(uint4*)(smc + nxt + 10240 + so + 16) = a3;
            *(uint4*)(smc + nxt + 20480 + so) = b0;  *(uint4*)(smc + nxt + 20480 + so + 16) = b1;
            *(uint4*)(smc + nxt + 30720 + so) = b2;  *(uint4*)(smc + nxt + 30720 + so + 16) = b3;
        }
        __syncthreads();
    }

    // ---- epilogue ----
    const float* xl = l ? g_xcur : x_in;
    float* dst = (l == LL - 1) ? outg : g_xcur;
#pragma unroll
    for (int i = 0; i < 2; i++) {
        size_t r0 = brow0 + wm + i * 16 + g, r1 = r0 + 8;
#pragma unroll
        for (int j = 0; j < 8; j++) {
            int c0 = no + wn + j * 8 + 2 * tig;
            float2 bv = *(const float2*)(biasg + l * NN + c0);
            // row r0 (d0,d1)
            {
                float2 xv = *(const float2*)(x_in + r0 * NN + c0);
                float2 lv = *(const float2*)(xl + r0 * NN + c0);
                float o0 = fmaf(xv.x, d[i][j][0] + bv.x, lv.x);
                float o1 = fmaf(xv.y, d[i][j][1] + bv.y, lv.y);
                *(float2*)(dst + r0 * NN + c0) = make_float2(o0, o1);
                if (l < LL - 1) {
                    uint32_t hh, ll;
                    bsplit2(o0, o1, hh, ll);
                    *(uint32_t*)(g_xh + r0 * NN + c0) = hh;
                    *(uint32_t*)(g_xl + r0 * NN + c0) = ll;
                }
            }
            // row r1 (d2,d3)
            {
                float2 xv = *(const float2*)(x_in + r1 * NN + c0);
                float2 lv = *(const float2*)(xl + r1 * NN + c0);
                float o0 = fmaf(xv.x, d[i][j][2] + bv.x, lv.x);
                float o1 = fmaf(xv.y, d[i][j][3] + bv.y, lv.y);
                *(float2*)(dst + r1 * NN + c0) = make_float2(o0, o1);
                if (l < LL - 1) {
                    uint32_t hh, ll;
                    bsplit2(o0, o1, hh, ll);
                    *(uint32_t*)(g_xh + r1 * NN + c0) = hh;
                    *(uint32_t*)(g_xl + r1 * NN + c0) = ll;
                }
            }
        }
    }
}

// =====================================================================
extern "C" void kernel_launch(void* const* d_in, const int* in_sizes, int n_in,
                              void* d_out, int out_size) {
    const float* x    = (const float*)d_in[0];
    const float* U    = (const float*)d_in[1];
    const float* V    = (const float*)d_in[2];
    const float* C    = (const float*)d_in[3];
    const float* bias = (const float*)d_in[4];
    const float* gw   = (const float*)d_in[5];
    float* out = (float*)d_out;

    prep_x<<<BATCH * NN / 256, 256>>>(x);
    prepV_k<<<LL * ER * NN / 256, 256>>>(V);
    prepU_k<<<LL * NN * ER / 256, 256>>>(U);
    prepC_k<<<LL * EE * RR * RR / 256, 256>>>(C);

    const int SM1 = 110592;   // max(double-buffer 81920, expert tiles 110592)
    const int SM2 = 81920;
    cudaFuncSetAttribute(gemm1_k, cudaFuncAttributeMaxDynamicSharedMemorySize, SM1);
    cudaFuncSetAttribute(gemm2_k, cudaFuncAttributeMaxDynamicSharedMemorySize, SM2);

    for (int l = 0; l < LL; l++) {
        gates_k<<<BATCH / 8, 256>>>(x, gw, l);
        gemm1_k<<<dim3(BATCH / 128, 4), 256, SM1>>>(l);
        gemm2_k<<<dim3(BATCH / 128, 8), 256, SM2>>>(x, bias, out, l);
    }
}

// round 5
// speedup vs baseline: 2.1941x; 1.0580x over previous
#include <cuda_runtime.h>
#include <cuda_bf16.h>
#include <cstdint>

#define BATCH 16384
#define NN    1024
#define EE    8
#define RR    64
#define ER    512
#define LL    3

// ---------------- static device scratch ----------------
__device__ float          g_xcur[BATCH * NN];
__device__ float          g_gates[BATCH * EE];
__device__ __nv_bfloat16  g_xh[BATCH * NN],  g_xl[BATCH * NN];
__device__ __nv_bfloat16  g_cph[BATCH * ER], g_cpl[BATCH * ER];
__device__ __nv_bfloat16  g_Vh[LL * ER * NN], g_Vl[LL * ER * NN];
__device__ __nv_bfloat16  g_Uh[LL * NN * ER], g_Ul[LL * NN * ER];
__device__ __nv_bfloat16  g_Ch[LL * EE * RR * RR], g_Cl[LL * EE * RR * RR];

// ---------------- helpers ----------------
__device__ __forceinline__ uint32_t smem_u32(const void* p) {
    uint32_t a;
    asm("{ .reg .u64 t; cvta.to.shared.u64 t, %1; cvt.u32.u64 %0, t; }" : "=r"(a) : "l"(p));
    return a;
}
__device__ __forceinline__ void ldsm4(uint32_t* r, uint32_t addr) {
    asm volatile("ldmatrix.sync.aligned.m8n8.x4.shared.b16 {%0,%1,%2,%3}, [%4];"
                 : "=r"(r[0]), "=r"(r[1]), "=r"(r[2]), "=r"(r[3]) : "r"(addr));
}
__device__ __forceinline__ void mma_bf16(float* d, const uint32_t* a, const uint32_t* b) {
    asm volatile(
        "mma.sync.aligned.m16n8k16.row.col.f32.bf16.bf16.f32 "
        "{%0,%1,%2,%3}, {%4,%5,%6,%7}, {%8,%9}, {%0,%1,%2,%3};"
        : "+f"(d[0]), "+f"(d[1]), "+f"(d[2]), "+f"(d[3])
        : "r"(a[0]), "r"(a[1]), "r"(a[2]), "r"(a[3]), "r"(b[0]), "r"(b[1]));
}
__device__ __forceinline__ void bsplit2(float a, float b, uint32_t& hi, uint32_t& lo) {
    __nv_bfloat16 ha = __float2bfloat16(a), hb = __float2bfloat16(b);
    __nv_bfloat16 la = __float2bfloat16(a - __bfloat162float(ha));
    __nv_bfloat16 lb = __float2bfloat16(b - __bfloat162float(hb));
    hi = (uint32_t)__bfloat16_as_ushort(ha) | ((uint32_t)__bfloat16_as_ushort(hb) << 16);
    lo = (uint32_t)__bfloat16_as_ushort(la) | ((uint32_t)__bfloat16_as_ushort(lb) << 16);
}
__device__ __forceinline__ void cp16(uint32_t dst, const void* src) {
    asm volatile("cp.async.cg.shared.global [%0], [%1], 16;" :: "r"(dst), "l"(src));
}
#define CP_COMMIT() asm volatile("cp.async.commit_group;" ::: "memory")
#define CP_WAIT1()  asm volatile("cp.async.wait_group 1;" ::: "memory")
#define CP_WAIT0()  asm volatile("cp.async.wait_group 0;" ::: "memory")

// ---------------- prep kernels ----------------
__global__ void prep_x(const float* __restrict__ x) {
    int i = blockIdx.x * 256 + threadIdx.x;
    uint32_t h, l; bsplit2(x[i], 0.f, h, l);
    g_xh[i] = __ushort_as_bfloat16((unsigned short)(h & 0xffff));
    g_xl[i] = __ushort_as_bfloat16((unsigned short)(l & 0xffff));
}
__global__ void prepV_k(const float* __restrict__ V) {
    int i = blockIdx.x * 256 + threadIdx.x;
    uint32_t h, l; bsplit2(V[i], 0.f, h, l);
    g_Vh[i] = __ushort_as_bfloat16((unsigned short)(h & 0xffff));
    g_Vl[i] = __ushort_as_bfloat16((unsigned short)(l & 0xffff));
}
__global__ void prepC_k(const float* __restrict__ C) {
    int i = blockIdx.x * 256 + threadIdx.x;
    uint32_t h, l; bsplit2(C[i], 0.f, h, l);
    g_Ch[i] = __ushort_as_bfloat16((unsigned short)(h & 0xffff));
    g_Cl[i] = __ushort_as_bfloat16((unsigned short)(l & 0xffff));
}
__global__ void prepU_k(const float* __restrict__ U) {
    int o = blockIdx.x * 256 + threadIdx.x;     // o = (l*NN + n)*ER + er
    int er = o & 511, n = (o >> 9) & 1023, l = o >> 19;
    float f = U[(((size_t)(l * EE + (er >> 6))) * NN + n) * RR + (er & 63)];
    uint32_t h, lo; bsplit2(f, 0.f, h, lo);
    g_Uh[o] = __ushort_as_bfloat16((unsigned short)(h & 0xffff));
    g_Ul[o] = __ushort_as_bfloat16((unsigned short)(lo & 0xffff));
}

// ---------------- gates (exact fp32) ----------------
__global__ void gates_k(const float* __restrict__ x_in, const float* __restrict__ gw, int l) {
    const float* xl = l ? g_xcur : x_in;
    int w = threadIdx.x >> 5, lane = threadIdx.x & 31;
    size_t row = (size_t)blockIdx.x * 8 + w;
    const float4* xr = (const float4*)(xl + row * NN);
    float acc[EE];
#pragma unroll
    for (int e = 0; e < EE; e++) acc[e] = 0.f;
#pragma unroll
    for (int i = 0; i < 8; i++) {
        float4 xv = xr[i * 32 + lane];
#pragma unroll
        for (int e = 0; e < EE; e++) {
            float4 wv = ((const float4*)(gw + e * NN))[i * 32 + lane];
            acc[e] += xv.x * wv.x + xv.y * wv.y + xv.z * wv.z + xv.w * wv.w;
        }
    }
#pragma unroll
    for (int off = 16; off > 0; off >>= 1)
#pragma unroll
        for (int e = 0; e < EE; e++) acc[e] += __shfl_xor_sync(0xffffffffu, acc[e], off);
    if (lane == 0) {
        float m = acc[0];
#pragma unroll
        for (int e = 1; e < EE; e++) m = fmaxf(m, acc[e]);
        float s = 0.f, pe[EE];
#pragma unroll
        for (int e = 0; e < EE; e++) { pe[e] = __expf(acc[e] - m); s += pe[e]; }
        float inv = 1.0f / s;
#pragma unroll
        for (int e = 0; e < EE; e++) g_gates[row * EE + e] = pe[e] * inv;
    }
}

// ---------------- stage layout (bytes) ----------------
// per stage (61440): Ah[256][80] @0, Al @20480, Bh[128][80] @40960, Bl @51200
#define STG   61440
#define S_AL  20480
#define S_BH  40960
#define S_BL  51200
// gemm1 expert-phase regions (reuse whole smem after mainloop):
#define RV_H(el)  ((el) * 73728)            // rv hi: 256x144
#define RV_L(el)  ((el) * 73728 + 36864)    // rv lo
#define OCT       147456                    // C tiles: el*18432 (+9216 lo)
#define SM1_SZ    184320
#define SM2_SZ    122880

// cp.async stage: A 256 rows x 64B (hi+lo), B 128 rows x 64B (hi+lo)
__device__ __forceinline__ void stage_panels(
    uint32_t sbase, int t,
    const __nv_bfloat16* Ah, const __nv_bfloat16* Al, int strideA,
    const __nv_bfloat16* Bh, const __nv_bfloat16* Bl, int strideB) {
    const int crow = t >> 2;
    const uint32_t cseg = (uint32_t)(t & 3) * 16;
#pragma unroll
    for (int it = 0; it < 4; it++) {
        int r = it * 64 + crow;
        uint32_t d = sbase + (uint32_t)r * 80 + cseg;
        cp16(d,        (const char*)(Ah + (size_t)r * strideA) + cseg);
        cp16(d + S_AL, (const char*)(Al + (size_t)r * strideA) + cseg);
    }
#pragma unroll
    for (int it = 0; it < 2; it++) {
        int r = it * 64 + crow;
        uint32_t d = sbase + S_BH + (uint32_t)r * 80 + cseg;
        cp16(d,                 (const char*)(Bh + (size_t)r * strideB) + cseg);
        cp16(d + (S_BL - S_BH), (const char*)(Bl + (size_t)r * strideB) + cseg);
    }
}

// ---------------- 256x128 tile, one k32 chunk; warp tile 64x64 ----------------
__device__ __forceinline__ void mma_block256(uint32_t base, int wm, int wn, int lr, int kc,
                                             float d[4][8][4]) {
    const uint32_t Ah = base, Al = base + S_AL, Bh = base + S_BH, Bl = base + S_BL;
#pragma unroll
    for (int q = 0; q < 2; q++) {
        uint32_t ah[4][4], al[4][4];
#pragma unroll
        for (int i = 0; i < 4; i++) {
            uint32_t ra = (uint32_t)((wm + i * 16 + lr) * 80 + (q * 16 + kc) * 2);
            ldsm4(ah[i], Ah + ra);
            ldsm4(al[i], Al + ra);
        }
        uint32_t bh[8][2], bl[8][2];
#pragma unroll
        for (int jj = 0; jj < 4; jj++) {
            uint32_t rb = (uint32_t)((wn + jj * 16 + lr) * 80 + (q * 16 + kc) * 2);
            uint32_t tp[4];
            ldsm4(tp, Bh + rb);
            bh[2 * jj][0] = tp[0]; bh[2 * jj + 1][0] = tp[1];
            bh[2 * jj][1] = tp[2]; bh[2 * jj + 1][1] = tp[3];
            ldsm4(tp, Bl + rb);
            bl[2 * jj][0] = tp[0]; bl[2 * jj + 1][0] = tp[1];
            bl[2 * jj][1] = tp[2]; bl[2 * jj + 1][1] = tp[3];
        }
#pragma unroll
        for (int i = 0; i < 4; i++)
#pragma unroll
            for (int j = 0; j < 8; j++) {
                mma_bf16(d[i][j], ah[i], bh[j]);
                mma_bf16(d[i][j], ah[i], bl[j]);
                mma_bf16(d[i][j], al[i], bh[j]);
            }
    }
}

// =====================================================================
// GEMM1 (v = x @ V^T) + fused expert chain -> c' hi/lo
// grid (BATCH/256, 4), 256 threads
// =====================================================================
__global__ void __launch_bounds__(256, 1) gemm1_k(int l) {
    extern __shared__ char smc[];
    const uint32_t sb = smem_u32(smc);
    const int t = threadIdx.x, w = t >> 5, lane = t & 31;
    const int lr = lane & 15, kc = (lane >> 4) * 8, g = lane >> 2, tig = lane & 3;
    const int wm = (w & 3) * 64, wn = (w >> 2) * 64;
    const size_t brow0 = (size_t)blockIdx.x * 256;
    const int no = blockIdx.y * 128;

    const __nv_bfloat16* pAh = g_xh + brow0 * NN;
    const __nv_bfloat16* pAl = g_xl + brow0 * NN;
    const __nv_bfloat16* pBh = g_Vh + (size_t)l * ER * NN + (size_t)no * NN;
    const __nv_bfloat16* pBl = g_Vl + (size_t)l * ER * NN + (size_t)no * NN;

    float d[4][8][4];
#pragma unroll
    for (int i = 0; i < 4; i++)
#pragma unroll
        for (int j = 0; j < 8; j++)
#pragma unroll
            for (int k = 0; k < 4; k++) d[i][j][k] = 0.f;

    stage_panels(sb, t, pAh, pAl, NN, pBh, pBl, NN);
    CP_COMMIT();

    for (int kt = 0; kt < 32; kt++) {
        const uint32_t cur = (uint32_t)(kt & 1) * STG;
        if (kt < 31) {
            int o = (kt + 1) * 32;
            stage_panels(sb + (cur ^ STG), t, pAh + o, pAl + o, NN, pBh + o, pBl + o, NN);
            CP_COMMIT();
            CP_WAIT1();
        } else {
            CP_WAIT0();
        }
        __syncthreads();
        mma_block256(sb + cur, wm, wn, lr, kc, d);
        __syncthreads();
    }

    // ---- write relu(v) split into rv tiles (pitch 144, per expert el=w>>2) ----
    const int el = w >> 2;
    {
#pragma unroll
        for (int i = 0; i < 4; i++) {
            int r0 = wm + i * 16 + g;
#pragma unroll
            for (int j = 0; j < 8; j++) {
                int c = j * 8 + 2 * tig;
                uint32_t h0, l0, h1, l1;
                bsplit2(fmaxf(d[i][j][0], 0.f), fmaxf(d[i][j][1], 0.f), h0, l0);
                bsplit2(fmaxf(d[i][j][2], 0.f), fmaxf(d[i][j][3], 0.f), h1, l1);
                uint32_t o0 = (uint32_t)(r0 * 144 + c * 2);
                uint32_t o1 = o0 + 8 * 144;
                *(uint32_t*)(smc + RV_H(el) + o0) = h0;
                *(uint32_t*)(smc + RV_H(el) + o1) = h1;
                *(uint32_t*)(smc + RV_L(el) + o0) = l0;
                *(uint32_t*)(smc + RV_L(el) + o1) = l1;
            }
        }
    }
    // ---- load C tiles (2 experts) ----
    {
        int el2 = t >> 7, r = (t >> 1) & 63, hf = t & 1;
        const __nv_bfloat16* sH = g_Ch +
            (((size_t)(l * EE + blockIdx.y * 2 + el2)) * RR + r) * RR + hf * 32;
        const __nv_bfloat16* sL = g_Cl +
            (((size_t)(l * EE + blockIdx.y * 2 + el2)) * RR + r) * RR + hf * 32;
        char* dH = smc + OCT + el2 * 18432 + r * 144 + hf * 64;
#pragma unroll
        for (int s4 = 0; s4 < 4; s4++) {
            *(uint4*)(dH + s4 * 16)        = *(const uint4*)(sH + s4 * 8);
            *(uint4*)(dH + 9216 + s4 * 16) = *(const uint4*)(sL + s4 * 8);
        }
    }
    __syncthreads();

    // ---- expert mma: c = rv @ C_e^T  (K=64) ----
#pragma unroll
    for (int i = 0; i < 4; i++)
#pragma unroll
        for (int j = 0; j < 8; j++)
#pragma unroll
            for (int k = 0; k < 4; k++) d[i][j][k] = 0.f;
    {
        const uint32_t Ah = sb + RV_H(el), Al = sb + RV_L(el);
        const uint32_t Bh = sb + OCT + el * 18432, Bl = Bh + 9216;
#pragma unroll
        for (int q = 0; q < 4; q++) {
            uint32_t ah[4][4], al[4][4];
#pragma unroll
            for (int i = 0; i < 4; i++) {
                uint32_t ra = (uint32_t)((wm + i * 16 + lr) * 144 + (q * 16 + kc) * 2);
                ldsm4(ah[i], Ah + ra);
                ldsm4(al[i], Al + ra);
            }
            uint32_t bh[8][2], bl[8][2];
#pragma unroll
            for (int jj = 0; jj < 4; jj++) {
                uint32_t rb = (uint32_t)((jj * 16 + lr) * 144 + (q * 16 + kc) * 2);
                uint32_t tp[4];
                ldsm4(tp, Bh + rb);
                bh[2 * jj][0] = tp[0]; bh[2 * jj + 1][0] = tp[1];
                bh[2 * jj][1] = tp[2]; bh[2 * jj + 1][1] = tp[3];
                ldsm4(tp, Bl + rb);
                bl[2 * jj][0] = tp[0]; bl[2 * jj + 1][0] = tp[1];
                bl[2 * jj][1] = tp[2]; bl[2 * jj + 1][1] = tp[3];
            }
#pragma unroll
            for (int i = 0; i < 4; i++)
#pragma unroll
                for (int j = 0; j < 8; j++) {
                    mma_bf16(d[i][j], ah[i], bh[j]);
                    mma_bf16(d[i][j], ah[i], bl[j]);
                    mma_bf16(d[i][j], al[i], bh[j]);
                }
        }
    }

    // ---- epilogue: c' = gate*relu(c) split -> global ----
    {
        const int e = blockIdx.y * 2 + el;
#pragma unroll
        for (int i = 0; i < 4; i++) {
            size_t r0 = brow0 + wm + i * 16 + g, r1 = r0 + 8;
            float g0 = g_gates[r0 * EE + e], g1 = g_gates[r1 * EE + e];
#pragma unroll
            for (int j = 0; j < 8; j++) {
                int cc = e * 64 + j * 8 + 2 * tig;
                uint32_t h0, l0, h1, l1;
                bsplit2(g0 * fmaxf(d[i][j][0], 0.f), g0 * fmaxf(d[i][j][1], 0.f), h0, l0);
                bsplit2(g1 * fmaxf(d[i][j][2], 0.f), g1 * fmaxf(d[i][j][3], 0.f), h1, l1);
                *(uint32_t*)(g_cph + r0 * ER + cc) = h0;
                *(uint32_t*)(g_cpl + r0 * ER + cc) = l0;
                *(uint32_t*)(g_cph + r1 * ER + cc) = h1;
                *(uint32_t*)(g_cpl + r1 * ER + cc) = l1;
            }
        }
    }
}

// =====================================================================
// GEMM2: x_next = x0 * (c' @ U^T + bias) + x_l ; emits split x_next
// grid (BATCH/256, 8), 256 threads
// =====================================================================
__global__ void __launch_bounds__(256, 1) gemm2_k(const float* __restrict__ x_in,
                                                  const float* __restrict__ biasg,
                                                  float* __restrict__ outg, int l) {
    extern __shared__ char smc[];
    const uint32_t sb = smem_u32(smc);
    const int t = threadIdx.x, w = t >> 5, lane = t & 31;
    const int lr = lane & 15, kc = (lane >> 4) * 8, g = lane >> 2, tig = lane & 3;
    const int wm = (w & 3) * 64, wn = (w >> 2) * 64;
    const size_t brow0 = (size_t)blockIdx.x * 256;
    const int no = blockIdx.y * 128;

    const __nv_bfloat16* pAh = g_cph + brow0 * ER;
    const __nv_bfloat16* pAl = g_cpl + brow0 * ER;
    const __nv_bfloat16* pBh = g_Uh + (size_t)l * NN * ER + (size_t)no * ER;
    const __nv_bfloat16* pBl = g_Ul + (size_t)l * NN * ER + (size_t)no * ER;

    float d[4][8][4];
#pragma unroll
    for (int i = 0; i < 4; i++)
#pragma unroll
        for (int j = 0; j < 8; j++)
#pragma unroll
            for (int k = 0; k < 4; k++) d[i][j][k] = 0.f;

    stage_panels(sb, t, pAh, pAl, ER, pBh, pBl, ER);
    CP_COMMIT();

    for (int kt = 0; kt < 16; kt++) {
        const uint32_t cur = (uint32_t)(kt & 1) * STG;
        if (kt < 15) {
            int o = (kt + 1) * 32;
            stage_panels(sb + (cur ^ STG), t, pAh + o, pAl + o, ER, pBh + o, pBl + o, ER);
            CP_COMMIT();
            CP_WAIT1();
        } else {
            CP_WAIT0();
        }
        __syncthreads();
        mma_block256(sb + cur, wm, wn, lr, kc, d);
        __syncthreads();
    }

    // ---- epilogue ----
    const float* xl = l ? g_xcur : x_in;
    float* dst = (l == LL - 1) ? outg : g_xcur;
#pragma unroll
    for (int i = 0; i < 4; i++) {
        size_t r0 = brow0 + wm + i * 16 + g, r1 = r0 + 8;
#pragma unroll
        for (int j = 0; j < 8; j++) {
            int c0 = no + wn + j * 8 + 2 * tig;
            float2 bv = *(const float2*)(biasg + l * NN + c0);
            {
                float2 xv = *(const float2*)(x_in + r0 * NN + c0);
                float2 lv = *(const float2*)(xl + r0 * NN + c0);
                float o0 = fmaf(xv.x, d[i][j][0] + bv.x, lv.x);
                float o1 = fmaf(xv.y, d[i][j][1] + bv.y, lv.y);
                *(float2*)(dst + r0 * NN + c0) = make_float2(o0, o1);
                if (l < LL - 1) {
                    uint32_t hh, ll;
                    bsplit2(o0, o1, hh, ll);
                    *(uint32_t*)(g_xh + r0 * NN + c0) = hh;
                    *(uint32_t*)(g_xl + r0 * NN + c0) = ll;
                }
            }
            {
                float2 xv = *(const float2*)(x_in + r1 * NN + c0);
                float2 lv = *(const float2*)(xl + r1 * NN + c0);
                float o0 = fmaf(xv.x, d[i][j][2] + bv.x, lv.x);
                float o1 = fmaf(xv.y, d[i][j][3] + bv.y, lv.y);
                *(float2*)(dst + r1 * NN + c0) = make_float2(o0, o1);
                if (l < LL - 1) {
                    uint32_t hh, ll;
                    bsplit2(o0, o1, hh, ll);
                    *(uint32_t*)(g_xh + r1 * NN + c0) = hh;
                    *(uint32_t*)(g_xl + r1 * NN + c0) = ll;
                }
            }
        }
    }
}

// =====================================================================
extern "C" void kernel_launch(void* const* d_in, const int* in_sizes, int n_in,
                              void* d_out, int out_size) {
    const float* x    = (const float*)d_in[0];
    const float* U    = (const float*)d_in[1];
    const float* V    = (const float*)d_in[2];
    const float* C    = (const float*)d_in[3];
    const float* bias = (const float*)d_in[4];
    const float* gw   = (const float*)d_in[5];
    float* out = (float*)d_out;

    prep_x<<<BATCH * NN / 256, 256>>>(x);
    prepV_k<<<LL * ER * NN / 256, 256>>>(V);
    prepU_k<<<LL * NN * ER / 256, 256>>>(U);
    prepC_k<<<LL * EE * RR * RR / 256, 256>>>(C);

    cudaFuncSetAttribute(gemm1_k, cudaFuncAttributeMaxDynamicSharedMemorySize, SM1_SZ);
    cudaFuncSetAttribute(gemm2_k, cudaFuncAttributeMaxDynamicSharedMemorySize, SM2_SZ);

    for (int l = 0; l < LL; l++) {
        gates_k<<<BATCH / 8, 256>>>(x, gw, l);
        gemm1_k<<<dim3(BATCH / 256, 4), 256, SM1_SZ>>>(l);
        gemm2_k<<<dim3(BATCH / 256, 8), 256, SM2_SZ>>>(x, bias, out, l);
    }
}

// round 6
// speedup vs baseline: 2.7432x; 1.2502x over previous
#include <cuda_runtime.h>
#include <cuda_fp16.h>
#include <cstdint>

#define BATCH 16384
#define NN    1024
#define EE    8
#define RR    64
#define ER    512
#define LL    3

// ---------------- static device scratch ----------------
__device__ float   g_xcur[BATCH * NN];
__device__ float   g_gates[BATCH * EE];
__device__ __half  g_xh[BATCH * NN],  g_xl[BATCH * NN];     // x split (A side)
__device__ __half  g_cph[BATCH * ER], g_cpl[BATCH * ER];    // c' split (A side)
__device__ __half  g_Vh[LL * ER * NN];                      // weights: fp16 hi only
__device__ __half  g_Uh[LL * NN * ER];
__device__ __half  g_Ch[LL * EE * RR * RR];

// ---------------- helpers ----------------
__device__ __forceinline__ uint32_t smem_u32(const void* p) {
    uint32_t a;
    asm("{ .reg .u64 t; cvta.to.shared.u64 t, %1; cvt.u32.u64 %0, t; }" : "=r"(a) : "l"(p));
    return a;
}
__device__ __forceinline__ void ldsm4(uint32_t* r, uint32_t addr) {
    asm volatile("ldmatrix.sync.aligned.m8n8.x4.shared.b16 {%0,%1,%2,%3}, [%4];"
                 : "=r"(r[0]), "=r"(r[1]), "=r"(r[2]), "=r"(r[3]) : "r"(addr));
}
__device__ __forceinline__ void mma_f16(float* d, const uint32_t* a, const uint32_t* b) {
    asm volatile(
        "mma.sync.aligned.m16n8k16.row.col.f32.f16.f16.f32 "
        "{%0,%1,%2,%3}, {%4,%5,%6,%7}, {%8,%9}, {%0,%1,%2,%3};"
        : "+f"(d[0]), "+f"(d[1]), "+f"(d[2]), "+f"(d[3])
        : "r"(a[0]), "r"(a[1]), "r"(a[2]), "r"(a[3]), "r"(b[0]), "r"(b[1]));
}
// split (a,b) into packed fp16x2 hi and lo
__device__ __forceinline__ void hsplit2(float a, float b, uint32_t& hi, uint32_t& lo) {
    __half ha = __float2half_rn(a), hb = __float2half_rn(b);
    __half la = __float2half_rn(a - __half2float(ha));
    __half lb = __float2half_rn(b - __half2float(hb));
    hi = (uint32_t)__half_as_ushort(ha) | ((uint32_t)__half_as_ushort(hb) << 16);
    lo = (uint32_t)__half_as_ushort(la) | ((uint32_t)__half_as_ushort(lb) << 16);
}
__device__ __forceinline__ void cp16(uint32_t dst, const void* src) {
    asm volatile("cp.async.cg.shared.global [%0], [%1], 16;" :: "r"(dst), "l"(src));
}
#define CP_COMMIT() asm volatile("cp.async.commit_group;" ::: "memory")
#define CP_WAIT1()  asm volatile("cp.async.wait_group 1;" ::: "memory")
#define CP_WAIT0()  asm volatile("cp.async.wait_group 0;" ::: "memory")

// ---------------- prep kernels ----------------
__global__ void prep_x(const float* __restrict__ x) {
    int i = blockIdx.x * 256 + threadIdx.x;
    float v = x[i];
    __half h = __float2half_rn(v);
    g_xh[i] = h;
    g_xl[i] = __float2half_rn(v - __half2float(h));
}
__global__ void prepV_k(const float* __restrict__ V) {
    int i = blockIdx.x * 256 + threadIdx.x;
    g_Vh[i] = __float2half_rn(V[i]);
}
__global__ void prepC_k(const float* __restrict__ C) {
    int i = blockIdx.x * 256 + threadIdx.x;
    g_Ch[i] = __float2half_rn(C[i]);
}
__global__ void prepU_k(const float* __restrict__ U) {
    int o = blockIdx.x * 256 + threadIdx.x;     // o = (l*NN + n)*ER + er
    int er = o & 511, n = (o >> 9) & 1023, l = o >> 19;
    g_Uh[o] = __float2half_rn(U[(((size_t)(l * EE + (er >> 6))) * NN + n) * RR + (er & 63)]);
}

// ---------------- gates (exact fp32) ----------------
__global__ void gates_k(const float* __restrict__ x_in, const float* __restrict__ gw, int l) {
    const float* xl = l ? g_xcur : x_in;
    int w = threadIdx.x >> 5, lane = threadIdx.x & 31;
    size_t row = (size_t)blockIdx.x * 8 + w;
    const float4* xr = (const float4*)(xl + row * NN);
    float acc[EE];
#pragma unroll
    for (int e = 0; e < EE; e++) acc[e] = 0.f;
#pragma unroll
    for (int i = 0; i < 8; i++) {
        float4 xv = xr[i * 32 + lane];
#pragma unroll
        for (int e = 0; e < EE; e++) {
            float4 wv = ((const float4*)(gw + e * NN))[i * 32 + lane];
            acc[e] += xv.x * wv.x + xv.y * wv.y + xv.z * wv.z + xv.w * wv.w;
        }
    }
#pragma unroll
    for (int off = 16; off > 0; off >>= 1)
#pragma unroll
        for (int e = 0; e < EE; e++) acc[e] += __shfl_xor_sync(0xffffffffu, acc[e], off);
    if (lane == 0) {
        float m = acc[0];
#pragma unroll
        for (int e = 1; e < EE; e++) m = fmaxf(m, acc[e]);
        float s = 0.f, pe[EE];
#pragma unroll
        for (int e = 0; e < EE; e++) { pe[e] = __expf(acc[e] - m); s += pe[e]; }
        float inv = 1.0f / s;
#pragma unroll
        for (int e = 0; e < EE; e++) g_gates[row * EE + e] = pe[e] * inv;
    }
}

// ---------------- stage layout (bytes) ----------------
// per stage (51200): Ah[256][80] @0, Al @20480, Bh[128][80] @40960
#define STG   51200
#define S_AL  20480
#define S_BH  40960
// gemm1 expert phase (after mainloop, reuse whole smem):
#define RV_H(el)  ((el) * 73728)            // rv hi: 256x144
#define RV_L(el)  ((el) * 73728 + 36864)    // rv lo
#define OCT       147456                    // C tiles (hi only): el*9216
#define SM1_SZ    165888
#define SM2_SZ    102400

// cp.async stage: A 256 rows x 64B hi + 64B lo, B 128 rows x 64B hi
__device__ __forceinline__ void stage_panels(
    uint32_t sbase, int t,
    const __half* Ah, const __half* Al, int strideA,
    const __half* Bh, int strideB) {
    const int crow = t >> 2;
    const uint32_t cseg = (uint32_t)(t & 3) * 16;
#pragma unroll
    for (int it = 0; it < 4; it++) {
        int r = it * 64 + crow;
        uint32_t d = sbase + (uint32_t)r * 80 + cseg;
        cp16(d,        (const char*)(Ah + (size_t)r * strideA) + cseg);
        cp16(d + S_AL, (const char*)(Al + (size_t)r * strideA) + cseg);
    }
#pragma unroll
    for (int it = 0; it < 2; it++) {
        int r = it * 64 + crow;
        cp16(sbase + S_BH + (uint32_t)r * 80 + cseg,
             (const char*)(Bh + (size_t)r * strideB) + cseg);
    }
}

// ---------------- 256x128 tile, one k32 chunk; warp tile 64x64; 2 products ----
__device__ __forceinline__ void mma_block256(uint32_t base, int wm, int wn, int lr, int kc,
                                             float d[4][8][4]) {
    const uint32_t Ah = base, Al = base + S_AL, Bh = base + S_BH;
#pragma unroll
    for (int q = 0; q < 2; q++) {
        uint32_t ah[4][4], al[4][4];
#pragma unroll
        for (int i = 0; i < 4; i++) {
            uint32_t ra = (uint32_t)((wm + i * 16 + lr) * 80 + (q * 16 + kc) * 2);
            ldsm4(ah[i], Ah + ra);
            ldsm4(al[i], Al + ra);
        }
        uint32_t bh[8][2];
#pragma unroll
        for (int jj = 0; jj < 4; jj++) {
            uint32_t rb = (uint32_t)((wn + jj * 16 + lr) * 80 + (q * 16 + kc) * 2);
            uint32_t tp[4];
            ldsm4(tp, Bh + rb);
            bh[2 * jj][0] = tp[0]; bh[2 * jj + 1][0] = tp[1];
            bh[2 * jj][1] = tp[2]; bh[2 * jj + 1][1] = tp[3];
        }
#pragma unroll
        for (int i = 0; i < 4; i++)
#pragma unroll
            for (int j = 0; j < 8; j++) {
                mma_f16(d[i][j], ah[i], bh[j]);
                mma_f16(d[i][j], al[i], bh[j]);
            }
    }
}

// =====================================================================
// GEMM1 (v = x @ V^T) + fused expert chain -> c' hi/lo
// grid (BATCH/256, 4), 256 threads
// =====================================================================
__global__ void __launch_bounds__(256, 1) gemm1_k(int l) {
    extern __shared__ char smc[];
    const uint32_t sb = smem_u32(smc);
    const int t = threadIdx.x, w = t >> 5, lane = t & 31;
    const int lr = lane & 15, kc = (lane >> 4) * 8, g = lane >> 2, tig = lane & 3;
    const int wm = (w & 3) * 64, wn = (w >> 2) * 64;
    const size_t brow0 = (size_t)blockIdx.x * 256;
    const int no = blockIdx.y * 128;

    const __half* pAh = g_xh + brow0 * NN;
    const __half* pAl = g_xl + brow0 * NN;
    const __half* pBh = g_Vh + (size_t)l * ER * NN + (size_t)no * NN;

    float d[4][8][4];
#pragma unroll
    for (int i = 0; i < 4; i++)
#pragma unroll
        for (int j = 0; j < 8; j++)
#pragma unroll
            for (int k = 0; k < 4; k++) d[i][j][k] = 0.f;

    stage_panels(sb, t, pAh, pAl, NN, pBh, NN);
    CP_COMMIT();

    for (int kt = 0; kt < 32; kt++) {
        const uint32_t cur = (uint32_t)(kt & 1) * STG;
        if (kt < 31) {
            int o = (kt + 1) * 32;
            stage_panels(sb + (cur ^ STG), t, pAh + o, pAl + o, NN, pBh + o, NN);
            CP_COMMIT();
            CP_WAIT1();
        } else {
            CP_WAIT0();
        }
        __syncthreads();
        mma_block256(sb + cur, wm, wn, lr, kc, d);
        __syncthreads();
    }

    // ---- write relu(v) split into rv tiles (pitch 144, expert el = w>>2) ----
    const int el = w >> 2;
    {
#pragma unroll
        for (int i = 0; i < 4; i++) {
            int r0 = wm + i * 16 + g;
#pragma unroll
            for (int j = 0; j < 8; j++) {
                int c = j * 8 + 2 * tig;
                uint32_t h0, l0, h1, l1;
                hsplit2(fmaxf(d[i][j][0], 0.f), fmaxf(d[i][j][1], 0.f), h0, l0);
                hsplit2(fmaxf(d[i][j][2], 0.f), fmaxf(d[i][j][3], 0.f), h1, l1);
                uint32_t o0 = (uint32_t)(r0 * 144 + c * 2);
                uint32_t o1 = o0 + 8 * 144;
                *(uint32_t*)(smc + RV_H(el) + o0) = h0;
                *(uint32_t*)(smc + RV_H(el) + o1) = h1;
                *(uint32_t*)(smc + RV_L(el) + o0) = l0;
                *(uint32_t*)(smc + RV_L(el) + o1) = l1;
            }
        }
    }
    // ---- load C tiles hi (2 experts) ----
    {
        int el2 = t >> 7, r = (t >> 1) & 63, hf = t & 1;
        const __half* sH = g_Ch +
            (((size_t)(l * EE + blockIdx.y * 2 + el2)) * RR + r) * RR + hf * 32;
        char* dH = smc + OCT + el2 * 9216 + r * 144 + hf * 64;
#pragma unroll
        for (int s4 = 0; s4 < 4; s4++)
            *(uint4*)(dH + s4 * 16) = *(const uint4*)(sH + s4 * 8);
    }
    __syncthreads();

    // ---- expert mma: c = rv @ C_e^T  (K=64, 2 products) ----
#pragma unroll
    for (int i = 0; i < 4; i++)
#pragma unroll
        for (int j = 0; j < 8; j++)
#pragma unroll
            for (int k = 0; k < 4; k++) d[i][j][k] = 0.f;
    {
        const uint32_t Ah = sb + RV_H(el), Al = sb + RV_L(el);
        const uint32_t Bh = sb + OCT + el * 9216;
#pragma unroll
        for (int q = 0; q < 4; q++) {
            uint32_t ah[4][4], al[4][4];
#pragma unroll
            for (int i = 0; i < 4; i++) {
                uint32_t ra = (uint32_t)((wm + i * 16 + lr) * 144 + (q * 16 + kc) * 2);
                ldsm4(ah[i], Ah + ra);
                ldsm4(al[i], Al + ra);
            }
            uint32_t bh[8][2];
#pragma unroll
            for (int jj = 0; jj < 4; jj++) {
                uint32_t rb = (uint32_t)((jj * 16 + lr) * 144 + (q * 16 + kc) * 2);
                uint32_t tp[4];
                ldsm4(tp, Bh + rb);
                bh[2 * jj][0] = tp[0]; bh[2 * jj + 1][0] = tp[1];
                bh[2 * jj][1] = tp[2]; bh[2 * jj + 1][1] = tp[3];
            }
#pragma unroll
            for (int i = 0; i < 4; i++)
#pragma unroll
                for (int j = 0; j < 8; j++) {
                    mma_f16(d[i][j], ah[i], bh[j]);
                    mma_f16(d[i][j], al[i], bh[j]);
                }
        }
    }

    // ---- epilogue: c' = gate*relu(c) split -> global ----
    {
        const int e = blockIdx.y * 2 + el;
#pragma unroll
        for (int i = 0; i < 4; i++) {
            size_t r0 = brow0 + wm + i * 16 + g, r1 = r0 + 8;
            float g0 = g_gates[r0 * EE + e], g1 = g_gates[r1 * EE + e];
#pragma unroll
            for (int j = 0; j < 8; j++) {
                int cc = e * 64 + j * 8 + 2 * tig;
                uint32_t h0, l0, h1, l1;
                hsplit2(g0 * fmaxf(d[i][j][0], 0.f), g0 * fmaxf(d[i][j][1], 0.f), h0, l0);
                hsplit2(g1 * fmaxf(d[i][j][2], 0.f), g1 * fmaxf(d[i][j][3], 0.f), h1, l1);
                *(uint32_t*)(g_cph + r0 * ER + cc) = h0;
                *(uint32_t*)(g_cpl + r0 * ER + cc) = l0;
                *(uint32_t*)(g_cph + r1 * ER + cc) = h1;
                *(uint32_t*)(g_cpl + r1 * ER + cc) = l1;
            }
        }
    }
}

// =====================================================================
// GEMM2: x_next = x0 * (c' @ U^T + bias) + x_l ; emits split x_next
// grid (BATCH/256, 8), 256 threads
// =====================================================================
__global__ void __launch_bounds__(256, 1) gemm2_k(const float* __restrict__ x_in,
                                                  const float* __restrict__ biasg,
                                                  float* __restrict__ outg, int l) {
    extern __shared__ char smc[];
    const uint32_t sb = smem_u32(smc);
    const int t = threadIdx.x, w = t >> 5, lane = t & 31;
    const int lr = lane & 15, kc = (lane >> 4) * 8, g = lane >> 2, tig = lane & 3;
    const int wm = (w & 3) * 64, wn = (w >> 2) * 64;
    const size_t brow0 = (size_t)blockIdx.x * 256;
    const int no = blockIdx.y * 128;

    const __half* pAh = g_cph + brow0 * ER;
    const __half* pAl = g_cpl + brow0 * ER;
    const __half* pBh = g_Uh + (size_t)l * NN * ER + (size_t)no * ER;

    float d[4][8][4];
#pragma unroll
    for (int i = 0; i < 4; i++)
#pragma unroll
        for (int j = 0; j < 8; j++)
#pragma unroll
            for (int k = 0; k < 4; k++) d[i][j][k] = 0.f;

    stage_panels(sb, t, pAh, pAl, ER, pBh, ER);
    CP_COMMIT();

    for (int kt = 0; kt < 16; kt++) {
        const uint32_t cur = (uint32_t)(kt & 1) * STG;
        if (kt < 15) {
            int o = (kt + 1) * 32;
            stage_panels(sb + (cur ^ STG), t, pAh + o, pAl + o, ER, pBh + o, ER);
            CP_COMMIT();
            CP_WAIT1();
        } else {
            CP_WAIT0();
        }
        __syncthreads();
        mma_block256(sb + cur, wm, wn, lr, kc, d);
        __syncthreads();
    }

    // ---- epilogue ----
    const float* xl = l ? g_xcur : x_in;
    float* dst = (l == LL - 1) ? outg : g_xcur;
#pragma unroll
    for (int i = 0; i < 4; i++) {
        size_t r0 = brow0 + wm + i * 16 + g, r1 = r0 + 8;
#pragma unroll
        for (int j = 0; j < 8; j++) {
            int c0 = no + wn + j * 8 + 2 * tig;
            float2 bv = *(const float2*)(biasg + l * NN + c0);
            {
                float2 xv = *(const float2*)(x_in + r0 * NN + c0);
                float2 lv = *(const float2*)(xl + r0 * NN + c0);
                float o0 = fmaf(xv.x, d[i][j][0] + bv.x, lv.x);
                float o1 = fmaf(xv.y, d[i][j][1] + bv.y, lv.y);
                *(float2*)(dst + r0 * NN + c0) = make_float2(o0, o1);
                if (l < LL - 1) {
                    uint32_t hh, ll;
                    hsplit2(o0, o1, hh, ll);
                    *(uint32_t*)(g_xh + r0 * NN + c0) = hh;
                    *(uint32_t*)(g_xl + r0 * NN + c0) = ll;
                }
            }
            {
                float2 xv = *(const float2*)(x_in + r1 * NN + c0);
                float2 lv = *(const float2*)(xl + r1 * NN + c0);
                float o0 = fmaf(xv.x, d[i][j][2] + bv.x, lv.x);
                float o1 = fmaf(xv.y, d[i][j][3] + bv.y, lv.y);
                *(float2*)(dst + r1 * NN + c0) = make_float2(o0, o1);
                if (l < LL - 1) {
                    uint32_t hh, ll;
                    hsplit2(o0, o1, hh, ll);
                    *(uint32_t*)(g_xh + r1 * NN + c0) = hh;
                    *(uint32_t*)(g_xl + r1 * NN + c0) = ll;
                }
            }
        }
    }
}

// =====================================================================
extern "C" void kernel_launch(void* const* d_in, const int* in_sizes, int n_in,
                              void* d_out, int out_size) {
    const float* x    = (const float*)d_in[0];
    const float* U    = (const float*)d_in[1];
    const float* V    = (const float*)d_in[2];
    const float* C    = (const float*)d_in[3];
    const float* bias = (const float*)d_in[4];
    const float* gw   = (const float*)d_in[5];
    float* out = (float*)d_out;

    prep_x<<<BATCH * NN / 256, 256>>>(x);
    prepV_k<<<LL * ER * NN / 256, 256>>>(V);
    prepU_k<<<LL * NN * ER / 256, 256>>>(U);
    prepC_k<<<LL * EE * RR * RR / 256, 256>>>(C);

    cudaFuncSetAttribute(gemm1_k, cudaFuncAttributeMaxDynamicSharedMemorySize, SM1_SZ);
    cudaFuncSetAttribute(gemm2_k, cudaFuncAttributeMaxDynamicSharedMemorySize, SM2_SZ);

    for (int l = 0; l < LL; l++) {
        gates_k<<<BATCH / 8, 256>>>(x, gw, l);
        gemm1_k<<<dim3(BATCH / 256, 4), 256, SM1_SZ>>>(l);
        gemm2_k<<<dim3(BATCH / 256, 8), 256, SM2_SZ>>>(x, bias, out, l);
    }
}

// round 7
// speedup vs baseline: 4.1359x; 1.5077x over previous
#include <cuda_runtime.h>
#include <cuda_fp16.h>
#include <cstdint>

#define BATCH 16384
#define NN    1024
#define EE    8
#define RR    64
#define ER    512
#define LL    3

// ---------------- static device scratch ----------------
__device__ float   g_xcur[BATCH * NN];
__device__ float   g_gates[BATCH * EE];
__device__ __half  g_xh[BATCH * NN];            // x_l fp16
__device__ __half  g_cph[BATCH * ER];           // c' fp16
__device__ __half  g_Vh[LL * ER * NN];          // weights fp16
__device__ __half  g_Uh[LL * NN * ER];
__device__ __half  g_Ch[LL * EE * RR * RR];

// ---------------- helpers ----------------
__device__ __forceinline__ uint32_t smem_u32(const void* p) {
    uint32_t a;
    asm("{ .reg .u64 t; cvta.to.shared.u64 t, %1; cvt.u32.u64 %0, t; }" : "=r"(a) : "l"(p));
    return a;
}
__device__ __forceinline__ void ldsm4(uint32_t* r, uint32_t addr) {
    asm volatile("ldmatrix.sync.aligned.m8n8.x4.shared.b16 {%0,%1,%2,%3}, [%4];"
                 : "=r"(r[0]), "=r"(r[1]), "=r"(r[2]), "=r"(r[3]) : "r"(addr));
}
__device__ __forceinline__ void mma_f16(float* d, const uint32_t* a, const uint32_t* b) {
    asm volatile(
        "mma.sync.aligned.m16n8k16.row.col.f32.f16.f16.f32 "
        "{%0,%1,%2,%3}, {%4,%5,%6,%7}, {%8,%9}, {%0,%1,%2,%3};"
        : "+f"(d[0]), "+f"(d[1]), "+f"(d[2]), "+f"(d[3])
        : "r"(a[0]), "r"(a[1]), "r"(a[2]), "r"(a[3]), "r"(b[0]), "r"(b[1]));
}
__device__ __forceinline__ uint32_t hpack2(float a, float b) {
    __half ha = __float2half_rn(a), hb = __float2half_rn(b);
    return (uint32_t)__half_as_ushort(ha) | ((uint32_t)__half_as_ushort(hb) << 16);
}
__device__ __forceinline__ void cp16(uint32_t dst, const void* src) {
    asm volatile("cp.async.cg.shared.global [%0], [%1], 16;" :: "r"(dst), "l"(src));
}
#define CP_COMMIT() asm volatile("cp.async.commit_group;" ::: "memory")
#define CP_WAIT1()  asm volatile("cp.async.wait_group 1;" ::: "memory")
#define CP_WAIT0()  asm volatile("cp.async.wait_group 0;" ::: "memory")

// ---------------- prep kernels ----------------
__global__ void prep_x(const float* __restrict__ x) {
    int i = blockIdx.x * 256 + threadIdx.x;
    g_xh[i] = __float2half_rn(x[i]);
}
__global__ void prepV_k(const float* __restrict__ V) {
    int i = blockIdx.x * 256 + threadIdx.x;
    g_Vh[i] = __float2half_rn(V[i]);
}
__global__ void prepC_k(const float* __restrict__ C) {
    int i = blockIdx.x * 256 + threadIdx.x;
    g_Ch[i] = __float2half_rn(C[i]);
}
__global__ void prepU_k(const float* __restrict__ U) {
    int o = blockIdx.x * 256 + threadIdx.x;     // o = (l*NN + n)*ER + er
    int er = o & 511, n = (o >> 9) & 1023, l = o >> 19;
    g_Uh[o] = __float2half_rn(U[(((size_t)(l * EE + (er >> 6))) * NN + n) * RR + (er & 63)]);
}

// ---------------- gates (exact fp32) ----------------
__global__ void gates_k(const float* __restrict__ x_in, const float* __restrict__ gw, int l) {
    const float* xl = l ? g_xcur : x_in;
    int w = threadIdx.x >> 5, lane = threadIdx.x & 31;
    size_t row = (size_t)blockIdx.x * 8 + w;
    const float4* xr = (const float4*)(xl + row * NN);
    float acc[EE];
#pragma unroll
    for (int e = 0; e < EE; e++) acc[e] = 0.f;
#pragma unroll
    for (int i = 0; i < 8; i++) {
        float4 xv = xr[i * 32 + lane];
#pragma unroll
        for (int e = 0; e < EE; e++) {
            float4 wv = ((const float4*)(gw + e * NN))[i * 32 + lane];
            acc[e] += xv.x * wv.x + xv.y * wv.y + xv.z * wv.z + xv.w * wv.w;
        }
    }
#pragma unroll
    for (int off = 16; off > 0; off >>= 1)
#pragma unroll
        for (int e = 0; e < EE; e++) acc[e] += __shfl_xor_sync(0xffffffffu, acc[e], off);
    if (lane == 0) {
        float m = acc[0];
#pragma unroll
        for (int e = 1; e < EE; e++) m = fmaxf(m, acc[e]);
        float s = 0.f, pe[EE];
#pragma unroll
        for (int e = 0; e < EE; e++) { pe[e] = __expf(acc[e] - m); s += pe[e]; }
        float inv = 1.0f / s;
#pragma unroll
        for (int e = 0; e < EE; e++) g_gates[row * EE + e] = pe[e] * inv;
    }
}

// ---------------- stage layout (bytes) ----------------
// per stage (30720): A[256][80] @0, B[128][80] @20480
#define STG   30720
#define S_BH  20480
// gemm1 expert phase (after mainloop, reuse whole smem):
#define RV_H(el)  ((el) * 36864)            // rv: 256x144 fp16 per expert
#define OCT       73728                     // C tiles: el*9216
#define SM1_SZ    92160
#define SM2_SZ    61440

// cp.async stage: A 256 rows x 64B, B 128 rows x 64B  (6 cp16 / thread)
__device__ __forceinline__ void stage_panels(
    uint32_t sbase, int t,
    const __half* A, int strideA, const __half* B, int strideB) {
    const int crow = t >> 2;
    const uint32_t cseg = (uint32_t)(t & 3) * 16;
#pragma unroll
    for (int it = 0; it < 4; it++) {
        int r = it * 64 + crow;
        cp16(sbase + (uint32_t)r * 80 + cseg, (const char*)(A + (size_t)r * strideA) + cseg);
    }
#pragma unroll
    for (int it = 0; it < 2; it++) {
        int r = it * 64 + crow;
        cp16(sbase + S_BH + (uint32_t)r * 80 + cseg,
             (const char*)(B + (size_t)r * strideB) + cseg);
    }
}

// ---------------- 256x128 tile, one k32 chunk; warp tile 64x64; 1 product ----
__device__ __forceinline__ void mma_block256(uint32_t base, int wm, int wn, int lr, int kc,
                                             float d[4][8][4]) {
    const uint32_t Ah = base, Bh = base + S_BH;
#pragma unroll
    for (int q = 0; q < 2; q++) {
        uint32_t ah[4][4];
#pragma unroll
        for (int i = 0; i < 4; i++) {
            uint32_t ra = (uint32_t)((wm + i * 16 + lr) * 80 + (q * 16 + kc) * 2);
            ldsm4(ah[i], Ah + ra);
        }
        uint32_t bh[8][2];
#pragma unroll
        for (int jj = 0; jj < 4; jj++) {
            uint32_t rb = (uint32_t)((wn + jj * 16 + lr) * 80 + (q * 16 + kc) * 2);
            uint32_t tp[4];
            ldsm4(tp, Bh + rb);
            bh[2 * jj][0] = tp[0]; bh[2 * jj + 1][0] = tp[1];
            bh[2 * jj][1] = tp[2]; bh[2 * jj + 1][1] = tp[3];
        }
#pragma unroll
        for (int i = 0; i < 4; i++)
#pragma unroll
            for (int j = 0; j < 8; j++)
                mma_f16(d[i][j], ah[i], bh[j]);
    }
}

// =====================================================================
// GEMM1 (v = x @ V^T) + fused expert chain -> c'
// grid (BATCH/256, 4), 256 threads
// =====================================================================
__global__ void __launch_bounds__(256) gemm1_k(int l) {
    extern __shared__ char smc[];
    const uint32_t sb = smem_u32(smc);
    const int t = threadIdx.x, w = t >> 5, lane = t & 31;
    const int lr = lane & 15, kc = (lane >> 4) * 8, g = lane >> 2, tig = lane & 3;
    const int wm = (w & 3) * 64, wn = (w >> 2) * 64;
    const size_t brow0 = (size_t)blockIdx.x * 256;
    const int no = blockIdx.y * 128;

    const __half* pA = g_xh + brow0 * NN;
    const __half* pB = g_Vh + (size_t)l * ER * NN + (size_t)no * NN;

    float d[4][8][4];
#pragma unroll
    for (int i = 0; i < 4; i++)
#pragma unroll
        for (int j = 0; j < 8; j++)
#pragma unroll
            for (int k = 0; k < 4; k++) d[i][j][k] = 0.f;

    stage_panels(sb, t, pA, NN, pB, NN);
    CP_COMMIT();

    for (int kt = 0; kt < 32; kt++) {
        const uint32_t cur = (uint32_t)(kt & 1) * STG;
        if (kt < 31) {
            int o = (kt + 1) * 32;
            stage_panels(sb + (cur ^ STG), t, pA + o, NN, pB + o, NN);
            CP_COMMIT();
            CP_WAIT1();
        } else {
            CP_WAIT0();
        }
        __syncthreads();
        mma_block256(sb + cur, wm, wn, lr, kc, d);
        __syncthreads();
    }

    // ---- write relu(v) -> rv tiles (pitch 144, expert el = w>>2) ----
    const int el = w >> 2;
    {
#pragma unroll
        for (int i = 0; i < 4; i++) {
            int r0 = wm + i * 16 + g;
#pragma unroll
            for (int j = 0; j < 8; j++) {
                int c = j * 8 + 2 * tig;
                uint32_t h0 = hpack2(fmaxf(d[i][j][0], 0.f), fmaxf(d[i][j][1], 0.f));
                uint32_t h1 = hpack2(fmaxf(d[i][j][2], 0.f), fmaxf(d[i][j][3], 0.f));
                uint32_t o0 = (uint32_t)(r0 * 144 + c * 2);
                *(uint32_t*)(smc + RV_H(el) + o0)           = h0;
                *(uint32_t*)(smc + RV_H(el) + o0 + 8 * 144) = h1;
            }
        }
    }
    // ---- load C tiles (2 experts) ----
    {
        int el2 = t >> 7, r = (t >> 1) & 63, hf = t & 1;
        const __half* sH = g_Ch +
            (((size_t)(l * EE + blockIdx.y * 2 + el2)) * RR + r) * RR + hf * 32;
        char* dH = smc + OCT + el2 * 9216 + r * 144 + hf * 64;
#pragma unroll
        for (int s4 = 0; s4 < 4; s4++)
            *(uint4*)(dH + s4 * 16) = *(const uint4*)(sH + s4 * 8);
    }
    __syncthreads();

    // ---- expert mma: c = rv @ C_e^T  (K=64) ----
#pragma unroll
    for (int i = 0; i < 4; i++)
#pragma unroll
        for (int j = 0; j < 8; j++)
#pragma unroll
            for (int k = 0; k < 4; k++) d[i][j][k] = 0.f;
    {
        const uint32_t Ah = sb + RV_H(el);
        const uint32_t Bh = sb + OCT + el * 9216;
#pragma unroll
        for (int q = 0; q < 4; q++) {
            uint32_t ah[4][4];
#pragma unroll
            for (int i = 0; i < 4; i++) {
                uint32_t ra = (uint32_t)((wm + i * 16 + lr) * 144 + (q * 16 + kc) * 2);
                ldsm4(ah[i], Ah + ra);
            }
            uint32_t bh[8][2];
#pragma unroll
            for (int jj = 0; jj < 4; jj++) {
                uint32_t rb = (uint32_t)((jj * 16 + lr) * 144 + (q * 16 + kc) * 2);
                uint32_t tp[4];
                ldsm4(tp, Bh + rb);
                bh[2 * jj][0] = tp[0]; bh[2 * jj + 1][0] = tp[1];
                bh[2 * jj][1] = tp[2]; bh[2 * jj + 1][1] = tp[3];
            }
#pragma unroll
            for (int i = 0; i < 4; i++)
#pragma unroll
                for (int j = 0; j < 8; j++)
                    mma_f16(d[i][j], ah[i], bh[j]);
        }
    }

    // ---- epilogue: c' = gate*relu(c) -> global fp16 ----
    {
        const int e = blockIdx.y * 2 + el;
#pragma unroll
        for (int i = 0; i < 4; i++) {
            size_t r0 = brow0 + wm + i * 16 + g, r1 = r0 + 8;
            float g0 = g_gates[r0 * EE + e], g1 = g_gates[r1 * EE + e];
#pragma unroll
            for (int j = 0; j < 8; j++) {
                int cc = e * 64 + j * 8 + 2 * tig;
                *(uint32_t*)(g_cph + r0 * ER + cc) =
                    hpack2(g0 * fmaxf(d[i][j][0], 0.f), g0 * fmaxf(d[i][j][1], 0.f));
                *(uint32_t*)(g_cph + r1 * ER + cc) =
                    hpack2(g1 * fmaxf(d[i][j][2], 0.f), g1 * fmaxf(d[i][j][3], 0.f));
            }
        }
    }
}

// =====================================================================
// GEMM2: x_next = x0 * (c' @ U^T + bias) + x_l ; emits fp16 x_next
// grid (BATCH/256, 8), 256 threads
// =====================================================================
__global__ void __launch_bounds__(256) gemm2_k(const float* __restrict__ x_in,
                                               const float* __restrict__ biasg,
                                               float* __restrict__ outg, int l) {
    extern __shared__ char smc[];
    const uint32_t sb = smem_u32(smc);
    const int t = threadIdx.x, w = t >> 5, lane = t & 31;
    const int lr = lane & 15, kc = (lane >> 4) * 8, g = lane >> 2, tig = lane & 3;
    const int wm = (w & 3) * 64, wn = (w >> 2) * 64;
    const size_t brow0 = (size_t)blockIdx.x * 256;
    const int no = blockIdx.y * 128;

    const __half* pA = g_cph + brow0 * ER;
    const __half* pB = g_Uh + (size_t)l * NN * ER + (size_t)no * ER;

    float d[4][8][4];
#pragma unroll
    for (int i = 0; i < 4; i++)
#pragma unroll
        for (int j = 0; j < 8; j++)
#pragma unroll
            for (int k = 0; k < 4; k++) d[i][j][k] = 0.f;

    stage_panels(sb, t, pA, ER, pB, ER);
    CP_COMMIT();

    for (int kt = 0; kt < 16; kt++) {
        const uint32_t cur = (uint32_t)(kt & 1) * STG;
        if (kt < 15) {
            int o = (kt + 1) * 32;
            stage_panels(sb + (cur ^ STG), t, pA + o, ER, pB + o, ER);
            CP_COMMIT();
            CP_WAIT1();
        } else {
            CP_WAIT0();
        }
        __syncthreads();
        mma_block256(sb + cur, wm, wn, lr, kc, d);
        __syncthreads();
    }

    // ---- epilogue ----
    const float* xl = l ? g_xcur : x_in;
    float* dst = (l == LL - 1) ? outg : g_xcur;
#pragma unroll
    for (int i = 0; i < 4; i++) {
        size_t r0 = brow0 + wm + i * 16 + g, r1 = r0 + 8;
#pragma unroll
        for (int j = 0; j < 8; j++) {
            int c0 = no + wn + j * 8 + 2 * tig;
            float2 bv = *(const float2*)(biasg + l * NN + c0);
            {
                float2 xv = *(const float2*)(x_in + r0 * NN + c0);
                float2 lv = *(const float2*)(xl + r0 * NN + c0);
                float o0 = fmaf(xv.x, d[i][j][0] + bv.x, lv.x);
                float o1 = fmaf(xv.y, d[i][j][1] + bv.y, lv.y);
                *(float2*)(dst + r0 * NN + c0) = make_float2(o0, o1);
                if (l < LL - 1)
                    *(uint32_t*)(g_xh + r0 * NN + c0) = hpack2(o0, o1);
            }
            {
                float2 xv = *(const float2*)(x_in + r1 * NN + c0);
                float2 lv = *(const float2*)(xl + r1 * NN + c0);
                float o0 = fmaf(xv.x, d[i][j][2] + bv.x, lv.x);
                float o1 = fmaf(xv.y, d[i][j][3] + bv.y, lv.y);
                *(float2*)(dst + r1 * NN + c0) = make_float2(o0, o1);
                if (l < LL - 1)
                    *(uint32_t*)(g_xh + r1 * NN + c0) = hpack2(o0, o1);
            }
        }
    }
}

// =====================================================================
extern "C" void kernel_launch(void* const* d_in, const int* in_sizes, int n_in,
                              void* d_out, int out_size) {
    const float* x    = (const float*)d_in[0];
    const float* U    = (const float*)d_in[1];
    const float* V    = (const float*)d_in[2];
    const float* C    = (const float*)d_in[3];
    const float* bias = (const float*)d_in[4];
    const float* gw   = (const float*)d_in[5];
    float* out = (float*)d_out;

    prep_x<<<BATCH * NN / 256, 256>>>(x);
    prepV_k<<<LL * ER * NN / 256, 256>>>(V);
    prepU_k<<<LL * NN * ER / 256, 256>>>(U);
    prepC_k<<<LL * EE * RR * RR / 256, 256>>>(C);

    cudaFuncSetAttribute(gemm1_k, cudaFuncAttributeMaxDynamicSharedMemorySize, SM1_SZ);
    cudaFuncSetAttribute(gemm2_k, cudaFuncAttributeMaxDynamicSharedMemorySize, SM2_SZ);

    for (int l = 0; l < LL; l++) {
        gates_k<<<BATCH / 8, 256>>>(x, gw, l);
        gemm1_k<<<dim3(BATCH / 256, 4), 256, SM1_SZ>>>(l);
        gemm2_k<<<dim3(BATCH / 256, 8), 256, SM2_SZ>>>(x, bias, out, l);
    }
}

// round 8
// speedup vs baseline: 4.9889x; 1.2062x over previous
#include <cuda_runtime.h>
#include <cuda_fp16.h>
#include <cstdint>

#define BATCH 16384
#define NN    1024
#define EE    8
#define RR    64
#define ER    512
#define LL    3

// ---------------- static device scratch ----------------
__device__ float   g_xcur[BATCH * NN];
__device__ float   g_gates[BATCH * EE];
__device__ __half  g_xh[BATCH * NN];            // x_l fp16
__device__ __half  g_cph[BATCH * ER];           // c' fp16
__device__ __half  g_Vh[LL * ER * NN];          // weights fp16
__device__ __half  g_Uh[LL * NN * ER];
__device__ __half  g_Ch[LL * EE * RR * RR];

// ---------------- helpers ----------------
__device__ __forceinline__ uint32_t smem_u32(const void* p) {
    uint32_t a;
    asm("{ .reg .u64 t; cvta.to.shared.u64 t, %1; cvt.u32.u64 %0, t; }" : "=r"(a) : "l"(p));
    return a;
}
__device__ __forceinline__ void ldsm4(uint32_t* r, uint32_t addr) {
    asm volatile("ldmatrix.sync.aligned.m8n8.x4.shared.b16 {%0,%1,%2,%3}, [%4];"
                 : "=r"(r[0]), "=r"(r[1]), "=r"(r[2]), "=r"(r[3]) : "r"(addr));
}
__device__ __forceinline__ void mma_f16(float* d, const uint32_t* a, const uint32_t* b) {
    asm volatile(
        "mma.sync.aligned.m16n8k16.row.col.f32.f16.f16.f32 "
        "{%0,%1,%2,%3}, {%4,%5,%6,%7}, {%8,%9}, {%0,%1,%2,%3};"
        : "+f"(d[0]), "+f"(d[1]), "+f"(d[2]), "+f"(d[3])
        : "r"(a[0]), "r"(a[1]), "r"(a[2]), "r"(a[3]), "r"(b[0]), "r"(b[1]));
}
__device__ __forceinline__ uint32_t hpack2(float a, float b) {
    __half ha = __float2half_rn(a), hb = __float2half_rn(b);
    return (uint32_t)__half_as_ushort(ha) | ((uint32_t)__half_as_ushort(hb) << 16);
}
__device__ __forceinline__ void cp16(uint32_t dst, const void* src) {
    asm volatile("cp.async.cg.shared.global [%0], [%1], 16;" :: "r"(dst), "l"(src));
}
#define CP_COMMIT() asm volatile("cp.async.commit_group;" ::: "memory")
#define CP_WAIT1()  asm volatile("cp.async.wait_group 1;" ::: "memory")
#define CP_WAIT0()  asm volatile("cp.async.wait_group 0;" ::: "memory")

// ---------------- prep kernels ----------------
__global__ void prep_x(const float* __restrict__ x) {
    int i = blockIdx.x * 256 + threadIdx.x;
    g_xh[i] = __float2half_rn(x[i]);
}
__global__ void prepV_k(const float* __restrict__ V) {
    int i = blockIdx.x * 256 + threadIdx.x;
    g_Vh[i] = __float2half_rn(V[i]);
}
__global__ void prepC_k(const float* __restrict__ C) {
    int i = blockIdx.x * 256 + threadIdx.x;
    g_Ch[i] = __float2half_rn(C[i]);
}
__global__ void prepU_k(const float* __restrict__ U) {
    int o = blockIdx.x * 256 + threadIdx.x;     // o = (l*NN + n)*ER + er
    int er = o & 511, n = (o >> 9) & 1023, l = o >> 19;
    g_Uh[o] = __float2half_rn(U[(((size_t)(l * EE + (er >> 6))) * NN + n) * RR + (er & 63)]);
}

// ---------------- gates (exact fp32) ----------------
__global__ void gates_k(const float* __restrict__ x_in, const float* __restrict__ gw, int l) {
    const float* xl = l ? g_xcur : x_in;
    int w = threadIdx.x >> 5, lane = threadIdx.x & 31;
    size_t row = (size_t)blockIdx.x * 8 + w;
    const float4* xr = (const float4*)(xl + row * NN);
    float acc[EE];
#pragma unroll
    for (int e = 0; e < EE; e++) acc[e] = 0.f;
#pragma unroll
    for (int i = 0; i < 8; i++) {
        float4 xv = xr[i * 32 + lane];
#pragma unroll
        for (int e = 0; e < EE; e++) {
            float4 wv = ((const float4*)(gw + e * NN))[i * 32 + lane];
            acc[e] += xv.x * wv.x + xv.y * wv.y + xv.z * wv.z + xv.w * wv.w;
        }
    }
#pragma unroll
    for (int off = 16; off > 0; off >>= 1)
#pragma unroll
        for (int e = 0; e < EE; e++) acc[e] += __shfl_xor_sync(0xffffffffu, acc[e], off);
    if (lane == 0) {
        float m = acc[0];
#pragma unroll
        for (int e = 1; e < EE; e++) m = fmaxf(m, acc[e]);
        float s = 0.f, pe[EE];
#pragma unroll
        for (int e = 0; e < EE; e++) { pe[e] = __expf(acc[e] - m); s += pe[e]; }
        float inv = 1.0f / s;
#pragma unroll
        for (int e = 0; e < EE; e++) g_gates[row * EE + e] = pe[e] * inv;
    }
}

// ---------------- stage layout (bytes) ----------------
// per stage (20480): A[128][80] @0, B[128][80] @10240 ; 3 stages
#define STG   20480
#define S_BH  10240
// gemm1 expert phase (after mainloop, reuse whole smem):
#define RV_H(el)  ((el) * 18432)            // rv: 128x144 fp16 per expert
#define OCT       36864                     // C tiles: el*9216
#define SM_SZ     61440

// cp.async stage: A 128 rows x 64B, B 128 rows x 64B  (4 cp16 / thread)
__device__ __forceinline__ void stage_panels(
    uint32_t sbase, int t,
    const __half* A, int strideA, const __half* B, int strideB) {
    const int crow = t >> 2;
    const uint32_t cseg = (uint32_t)(t & 3) * 16;
#pragma unroll
    for (int it = 0; it < 2; it++) {
        int r = it * 64 + crow;
        cp16(sbase + (uint32_t)r * 80 + cseg, (const char*)(A + (size_t)r * strideA) + cseg);
        cp16(sbase + S_BH + (uint32_t)r * 80 + cseg,
             (const char*)(B + (size_t)r * strideB) + cseg);
    }
}

// ---------------- 128x128 tile, one k32 chunk; warp tile 32x64 ----------------
__device__ __forceinline__ void mma_block128(uint32_t base, int wm, int wn, int lr, int kc,
                                             float d[2][8][4]) {
    const uint32_t Ah = base, Bh = base + S_BH;
#pragma unroll
    for (int q = 0; q < 2; q++) {
        uint32_t ah[2][4];
#pragma unroll
        for (int i = 0; i < 2; i++) {
            uint32_t ra = (uint32_t)((wm + i * 16 + lr) * 80 + (q * 16 + kc) * 2);
            ldsm4(ah[i], Ah + ra);
        }
        uint32_t bh[8][2];
#pragma unroll
        for (int jj = 0; jj < 4; jj++) {
            uint32_t rb = (uint32_t)((wn + jj * 16 + lr) * 80 + (q * 16 + kc) * 2);
            uint32_t tp[4];
            ldsm4(tp, Bh + rb);
            bh[2 * jj][0] = tp[0]; bh[2 * jj + 1][0] = tp[1];
            bh[2 * jj][1] = tp[2]; bh[2 * jj + 1][1] = tp[3];
        }
#pragma unroll
        for (int i = 0; i < 2; i++)
#pragma unroll
            for (int j = 0; j < 8; j++)
                mma_f16(d[i][j], ah[i], bh[j]);
    }
}

// 3-buffer mainloop, ONE __syncthreads per chunk.
// Keeps 2 cp.async groups in flight; stage kt+2 is issued after the sync,
// into the buffer last read at iteration kt-1.
#define MAINLOOP(NK, pA, sA, pB, sB)                                          \
    stage_panels(sb, t, pA, sA, pB, sB); CP_COMMIT();                         \
    stage_panels(sb + STG, t, pA + 32, sA, pB + 32, sB); CP_COMMIT();         \
    _Pragma("unroll 1")                                                       \
    for (int kt = 0; kt < (NK); kt++) {                                       \
        if (kt + 1 < (NK)) { CP_WAIT1(); } else { CP_WAIT0(); }               \
        __syncthreads();                                                      \
        if (kt + 2 < (NK)) {                                                  \
            int bi = (kt + 2) % 3;                                            \
            stage_panels(sb + (uint32_t)bi * STG, t,                          \
                         pA + (kt + 2) * 32, sA, pB + (kt + 2) * 32, sB);     \
            CP_COMMIT();                                                      \
        }                                                                     \
        mma_block128(sb + (uint32_t)(kt % 3) * STG, wm, wn, lr, kc, d);       \
    }

// =====================================================================
// GEMM1 (v = x @ V^T) + fused expert chain -> c'
// grid (BATCH/128, 4), 256 threads, 2 CTAs/SM
// =====================================================================
__global__ void __launch_bounds__(256, 2) gemm1_k(int l) {
    extern __shared__ char smc[];
    const uint32_t sb = smem_u32(smc);
    const int t = threadIdx.x, w = t >> 5, lane = t & 31;
    const int lr = lane & 15, kc = (lane >> 4) * 8, g = lane >> 2, tig = lane & 3;
    const int wm = (w & 3) * 32, wn = (w >> 2) * 64;
    const size_t brow0 = (size_t)blockIdx.x * 128;
    const int no = blockIdx.y * 128;

    const __half* pA = g_xh + brow0 * NN;
    const __half* pB = g_Vh + (size_t)l * ER * NN + (size_t)no * NN;

    float d[2][8][4];
#pragma unroll
    for (int i = 0; i < 2; i++)
#pragma unroll
        for (int j = 0; j < 8; j++)
#pragma unroll
            for (int k = 0; k < 4; k++) d[i][j][k] = 0.f;

    MAINLOOP(32, pA, NN, pB, NN)
    __syncthreads();   // mainloop done before smem reuse

    // ---- write relu(v) -> rv tiles (pitch 144, expert el = w>>2) ----
    const int el = w >> 2;
    {
#pragma unroll
        for (int i = 0; i < 2; i++) {
            int r0 = wm + i * 16 + g;
#pragma unroll
            for (int j = 0; j < 8; j++) {
                int c = j * 8 + 2 * tig;
                uint32_t h0 = hpack2(fmaxf(d[i][j][0], 0.f), fmaxf(d[i][j][1], 0.f));
                uint32_t h1 = hpack2(fmaxf(d[i][j][2], 0.f), fmaxf(d[i][j][3], 0.f));
                uint32_t o0 = (uint32_t)(r0 * 144 + c * 2);
                *(uint32_t*)(smc + RV_H(el) + o0)           = h0;
                *(uint32_t*)(smc + RV_H(el) + o0 + 8 * 144) = h1;
            }
        }
    }
    // ---- load C tiles (2 experts) ----
    {
        int el2 = t >> 7, r = (t >> 1) & 63, hf = t & 1;
        const __half* sH = g_Ch +
            (((size_t)(l * EE + blockIdx.y * 2 + el2)) * RR + r) * RR + hf * 32;
        char* dH = smc + OCT + el2 * 9216 + r * 144 + hf * 64;
#pragma unroll
        for (int s4 = 0; s4 < 4; s4++)
            *(uint4*)(dH + s4 * 16) = *(const uint4*)(sH + s4 * 8);
    }
    __syncthreads();

    // ---- expert mma: c = rv @ C_e^T  (K=64) ----
#pragma unroll
    for (int i = 0; i < 2; i++)
#pragma unroll
        for (int j = 0; j < 8; j++)
#pragma unroll
            for (int k = 0; k < 4; k++) d[i][j][k] = 0.f;
    {
        const uint32_t Ah = sb + RV_H(el);
        const uint32_t Bh = sb + OCT + el * 9216;
#pragma unroll
        for (int q = 0; q < 4; q++) {
            uint32_t ah[2][4];
#pragma unroll
            for (int i = 0; i < 2; i++) {
                uint32_t ra = (uint32_t)((wm + i * 16 + lr) * 144 + (q * 16 + kc) * 2);
                ldsm4(ah[i], Ah + ra);
            }
            uint32_t bh[8][2];
#pragma unroll
            for (int jj = 0; jj < 4; jj++) {
                uint32_t rb = (uint32_t)((jj * 16 + lr) * 144 + (q * 16 + kc) * 2);
                uint32_t tp[4];
                ldsm4(tp, Bh + rb);
                bh[2 * jj][0] = tp[0]; bh[2 * jj + 1][0] = tp[1];
                bh[2 * jj][1] = tp[2]; bh[2 * jj + 1][1] = tp[3];
            }
#pragma unroll
            for (int i = 0; i < 2; i++)
#pragma unroll
                for (int j = 0; j < 8; j++)
                    mma_f16(d[i][j], ah[i], bh[j]);
        }
    }

    // ---- epilogue: c' = gate*relu(c) -> global fp16 ----
    {
        const int e = blockIdx.y * 2 + el;
#pragma unroll
        for (int i = 0; i < 2; i++) {
            size_t r0 = brow0 + wm + i * 16 + g, r1 = r0 + 8;
            float g0 = g_gates[r0 * EE + e], g1 = g_gates[r1 * EE + e];
#pragma unroll
            for (int j = 0; j < 8; j++) {
                int cc = e * 64 + j * 8 + 2 * tig;
                *(uint32_t*)(g_cph + r0 * ER + cc) =
                    hpack2(g0 * fmaxf(d[i][j][0], 0.f), g0 * fmaxf(d[i][j][1], 0.f));
                *(uint32_t*)(g_cph + r1 * ER + cc) =
                    hpack2(g1 * fmaxf(d[i][j][2], 0.f), g1 * fmaxf(d[i][j][3], 0.f));
            }
        }
    }
}

// =====================================================================
// GEMM2: x_next = x0 * (c' @ U^T + bias) + x_l ; emits fp16 x_next
// grid (BATCH/128, 8), 256 threads, 2 CTAs/SM
// =====================================================================
__global__ void __launch_bounds__(256, 2) gemm2_k(const float* __restrict__ x_in,
                                                  const float* __restrict__ biasg,
                                                  float* __restrict__ outg, int l) {
    extern __shared__ char smc[];
    const uint32_t sb = smem_u32(smc);
    const int t = threadIdx.x, w = t >> 5, lane = t & 31;
    const int lr = lane & 15, kc = (lane >> 4) * 8, g = lane >> 2, tig = lane & 3;
    const int wm = (w & 3) * 32, wn = (w >> 2) * 64;
    const size_t brow0 = (size_t)blockIdx.x * 128;
    const int no = blockIdx.y * 128;

    const __half* pA = g_cph + brow0 * ER;
    const __half* pB = g_Uh + (size_t)l * NN * ER + (size_t)no * ER;

    float d[2][8][4];
#pragma unroll
    for (int i = 0; i < 2; i++)
#pragma unroll
        for (int j = 0; j < 8; j++)
#pragma unroll
            for (int k = 0; k < 4; k++) d[i][j][k] = 0.f;

    MAINLOOP(16, pA, ER, pB, ER)

    // ---- epilogue ----
    const float* xl = l ? g_xcur : x_in;
    float* dst = (l == LL - 1) ? outg : g_xcur;
#pragma unroll
    for (int i = 0; i < 2; i++) {
        size_t r0 = brow0 + wm + i * 16 + g, r1 = r0 + 8;
#pragma unroll
        for (int j = 0; j < 8; j++) {
            int c0 = no + wn + j * 8 + 2 * tig;
            float2 bv = *(const float2*)(biasg + l * NN + c0);
            {
                float2 xv = *(const float2*)(x_in + r0 * NN + c0);
                float2 lv = *(const float2*)(xl + r0 * NN + c0);
                float o0 = fmaf(xv.x, d[i][j][0] + bv.x, lv.x);
                float o1 = fmaf(xv.y, d[i][j][1] + bv.y, lv.y);
                *(float2*)(dst + r0 * NN + c0) = make_float2(o0, o1);
                if (l < LL - 1)
                    *(uint32_t*)(g_xh + r0 * NN + c0) = hpack2(o0, o1);
            }
            {
                float2 xv = *(const float2*)(x_in + r1 * NN + c0);
                float2 lv = *(const float2*)(xl + r1 * NN + c0);
                float o0 = fmaf(xv.x, d[i][j][2] + bv.x, lv.x);
                float o1 = fmaf(xv.y, d[i][j][3] + bv.y, lv.y);
                *(float2*)(dst + r1 * NN + c0) = make_float2(o0, o1);
                if (l < LL - 1)
                    *(uint32_t*)(g_xh + r1 * NN + c0) = hpack2(o0, o1);
            }
        }
    }
}

// =====================================================================
extern "C" void kernel_launch(void* const* d_in, const int* in_sizes, int n_in,
                              void* d_out, int out_size) {
    const float* x    = (const float*)d_in[0];
    const float* U    = (const float*)d_in[1];
    const float* V    = (const float*)d_in[2];
    const float* C    = (const float*)d_in[3];
    const float* bias = (const float*)d_in[4];
    const float* gw   = (const float*)d_in[5];
    float* out = (float*)d_out;

    prep_x<<<BATCH * NN / 256, 256>>>(x);
    prepV_k<<<LL * ER * NN / 256, 256>>>(V);
    prepU_k<<<LL * NN * ER / 256, 256>>>(U);
    prepC_k<<<LL * EE * RR * RR / 256, 256>>>(C);

    cudaFuncSetAttribute(gemm1_k, cudaFuncAttributeMaxDynamicSharedMemorySize, SM_SZ);
    cudaFuncSetAttribute(gemm2_k, cudaFuncAttributeMaxDynamicSharedMemorySize, SM_SZ);

    for (int l = 0; l < LL; l++) {
        gates_k<<<BATCH / 8, 256>>>(x, gw, l);
        gemm1_k<<<dim3(BATCH / 128, 4), 256, SM_SZ>>>(l);
        gemm2_k<<<dim3(BATCH / 128, 8), 256, SM_SZ>>>(x, bias, out, l);
    }
}